// round 2
// baseline (speedup 1.0000x reference)
#include <cuda_runtime.h>

// ============================================================================
// NETWORK_OF_DANS — round 1 baseline
//
// 3 fused layer kernels. Each computes
//     pre = A1 @ B1^T + bias1 (+ A2 @ B2^T + bias2)      [512, 32768]
// as a 128x128x8-tiled SIMT fp32 GEMM using packed FFMA2 (fma.rn.f32x2),
// then applies the shared Simple_DAN (32 -> 15 -> 8 -> 1, leaky_relu 0.01)
// per node in the epilogue (via smem restage), emitting h [512, 1024].
// Pre-activations never touch HBM.
// ============================================================================

#define TILE_M 128
#define TILE_N 128
#define TILE_K 8
#define NTH 256

__device__ float g_h0[512 * 1024];
__device__ float g_h1[512 * 1024];

__device__ __forceinline__ float lrelu(float v) { return v > 0.0f ? v : 0.01f * v; }

__device__ __forceinline__ unsigned long long pack2(float lo, float hi) {
    unsigned long long r;
    asm("mov.b64 %0, {%1, %2};" : "=l"(r) : "f"(lo), "f"(hi));
    return r;
}
__device__ __forceinline__ void unpack2(unsigned long long v, float& lo, float& hi) {
    asm("mov.b64 {%0, %1}, %2;" : "=f"(lo), "=f"(hi) : "l"(v));
}
__device__ __forceinline__ void ffma2(unsigned long long& d, unsigned long long a,
                                      unsigned long long b) {
    asm("fma.rn.f32x2 %0, %1, %2, %3;" : "=l"(d) : "l"(a), "l"(b), "l"(d));
}

__global__ __launch_bounds__(NTH, 2)
void dan_layer_kernel(const float* __restrict__ A1, const float* __restrict__ B1,
                      const float* __restrict__ bias1,
                      const float* __restrict__ A2, const float* __restrict__ B2,
                      const float* __restrict__ bias2,
                      const float* __restrict__ Dw1, const float* __restrict__ Db1,
                      const float* __restrict__ Dw2, const float* __restrict__ Db2,
                      const float* __restrict__ Dw3, const float* __restrict__ Db3,
                      int layer_idx, int two_inputs,
                      float* __restrict__ out)
{
    // A tile stored as duplicated f32 pairs so FFMA2 broadcast operand is a
    // single LDS.64 (no per-k mov.b64 in the hot loop). Pads kill conflicts.
    __shared__ __align__(16) unsigned long long As2[TILE_K][130];
    __shared__ __align__(16) float Bs[TILE_K][132];
    __shared__ __align__(16) float ep[64][129];   // epilogue restage (row pad 1)
    __shared__ float sDw1[15 * 32];
    __shared__ float sDb1[15];
    __shared__ float sDw2[8 * 15];
    __shared__ float sDb2[8];
    __shared__ float sDw3[8];
    __shared__ float sDb3[1];

    const int tid = threadIdx.x;
    const int tx = tid & 15;     // n-dim thread coord (8 cols each)
    const int ty = tid >> 4;     // m-dim thread coord (8 rows each)
    const int bm = blockIdx.x * TILE_M;   // batch offset   (gridDim.x = 4)
    const int bn = blockIdx.y * TILE_N;   // out-col offset (gridDim.y = 256)

    // --- stage DAN weights (folded one-hot layer code into first-layer bias) ---
    for (int i = tid; i < 15 * 32; i += NTH)
        sDw1[i] = Dw1[(i >> 5) * 35 + (i & 31)];
    if (tid < 15) sDb1[tid] = Db1[tid] + Dw1[tid * 35 + 32 + layer_idx];
    if (tid >= 32 && tid < 152) sDw2[tid - 32] = Dw2[tid - 32];
    if (tid >= 160 && tid < 168) sDb2[tid - 160] = Db2[tid - 160];
    if (tid >= 168 && tid < 176) sDw3[tid - 168] = Dw3[tid - 168];
    if (tid == 176) sDb3[0] = Db3[0];

    // --- GEMM: acc[i][jj] = packed pair over columns (tx*8 + jj*2 + {0,1}) ---
    unsigned long long acc[8][4];
#pragma unroll
    for (int i = 0; i < 8; i++)
#pragma unroll
        for (int j = 0; j < 4; j++) acc[i][j] = 0ULL;

    const int ld_row = tid >> 1;        // 0..127 (row within tile, A and B)
    const int ld_k   = (tid & 1) * 4;   // 0 or 4 (k sub-offset, float4)

    const int total = two_inputs ? 256 : 128;  // K-tiles (K=1024 per input)

    float4 ra, rb;
    // prologue: load + store tile 0
    ra = *(const float4*)(A1 + (bm + ld_row) * 1024 + ld_k);
    rb = *(const float4*)(B1 + (bn + ld_row) * 1024 + ld_k);
    As2[ld_k + 0][ld_row] = pack2(ra.x, ra.x);
    As2[ld_k + 1][ld_row] = pack2(ra.y, ra.y);
    As2[ld_k + 2][ld_row] = pack2(ra.z, ra.z);
    As2[ld_k + 3][ld_row] = pack2(ra.w, ra.w);
    Bs[ld_k + 0][ld_row] = rb.x;
    Bs[ld_k + 1][ld_row] = rb.y;
    Bs[ld_k + 2][ld_row] = rb.z;
    Bs[ld_k + 3][ld_row] = rb.w;

    for (int t = 0; t < total; ++t) {
        __syncthreads();  // tile t visible in smem

        if (t + 1 < total) {  // prefetch next tile into registers
            const int tn = t + 1;
            const float* Ap = (tn < 128) ? A1 : A2;
            const float* Bp = (tn < 128) ? B1 : B2;
            const int k0 = (tn & 127) * TILE_K;
            ra = *(const float4*)(Ap + (bm + ld_row) * 1024 + k0 + ld_k);
            rb = *(const float4*)(Bp + (bn + ld_row) * 1024 + k0 + ld_k);
        }

#pragma unroll
        for (int k = 0; k < TILE_K; ++k) {
            unsigned long long ap[8];
            ulonglong2 a0 = *(const ulonglong2*)&As2[k][ty * 8 + 0];
            ulonglong2 a1 = *(const ulonglong2*)&As2[k][ty * 8 + 2];
            ulonglong2 a2 = *(const ulonglong2*)&As2[k][ty * 8 + 4];
            ulonglong2 a3 = *(const ulonglong2*)&As2[k][ty * 8 + 6];
            ap[0] = a0.x; ap[1] = a0.y; ap[2] = a1.x; ap[3] = a1.y;
            ap[4] = a2.x; ap[5] = a2.y; ap[6] = a3.x; ap[7] = a3.y;
            ulonglong2 b0 = *(const ulonglong2*)&Bs[k][tx * 8 + 0];
            ulonglong2 b1 = *(const ulonglong2*)&Bs[k][tx * 8 + 4];
            unsigned long long bp[4] = {b0.x, b0.y, b1.x, b1.y};
#pragma unroll
            for (int i = 0; i < 8; i++)
#pragma unroll
                for (int jj = 0; jj < 4; jj++)
                    ffma2(acc[i][jj], ap[i], bp[jj]);
        }

        __syncthreads();  // done reading tile t

        if (t + 1 < total) {  // commit prefetched tile
            As2[ld_k + 0][ld_row] = pack2(ra.x, ra.x);
            As2[ld_k + 1][ld_row] = pack2(ra.y, ra.y);
            As2[ld_k + 2][ld_row] = pack2(ra.z, ra.z);
            As2[ld_k + 3][ld_row] = pack2(ra.w, ra.w);
            Bs[ld_k + 0][ld_row] = rb.x;
            Bs[ld_k + 1][ld_row] = rb.y;
            Bs[ld_k + 2][ld_row] = rb.z;
            Bs[ld_k + 3][ld_row] = rb.w;
        }
    }

    // --- pre-activation bias for this thread's 8 columns ---
    float bcol[8];
#pragma unroll
    for (int j = 0; j < 8; j++) {
        const int ng = bn + tx * 8 + j;
        float s = bias1[ng];
        if (two_inputs) s += bias2[ng];
        bcol[j] = s;
    }

    // --- DAN epilogue: restage 64 rows x 128 cols at a time, then per-(row,node)
    //     threads run the 32->15->8->1 MLP. Row pad 129 => conflict-free reads. ---
    const int r  = tid & 63;   // row within half
    const int nd = tid >> 6;   // node within tile (TILE_N = 4 nodes x 32 ch)

    for (int h = 0; h < 2; ++h) {
        __syncthreads();
        if ((ty >> 3) == h) {
            const int tyl = (ty & 7) * 8;
#pragma unroll
            for (int i = 0; i < 8; i++)
#pragma unroll
                for (int jj = 0; jj < 4; jj++) {
                    float lo, hi;
                    unpack2(acc[i][jj], lo, hi);
                    ep[tyl + i][tx * 8 + jj * 2 + 0] = lo + bcol[jj * 2 + 0];
                    ep[tyl + i][tx * 8 + jj * 2 + 1] = hi + bcol[jj * 2 + 1];
                }
        }
        __syncthreads();

        float z[32];
#pragma unroll
        for (int c = 0; c < 32; c++) z[c] = ep[r][nd * 32 + c];

        float h1v[15];
#pragma unroll
        for (int u = 0; u < 15; u++) {
            float s = sDb1[u];
#pragma unroll
            for (int c = 0; c < 32; c++) s = fmaf(sDw1[u * 32 + c], z[c], s);
            h1v[u] = lrelu(s);
        }
        float o = sDb3[0];
#pragma unroll
        for (int v = 0; v < 8; v++) {
            float s = sDb2[v];
#pragma unroll
            for (int u = 0; u < 15; u++) s = fmaf(sDw2[v * 15 + u], h1v[u], s);
            o = fmaf(sDw3[v], lrelu(s), o);
        }
        out[(bm + h * 64 + r) * 1024 + (bn >> 5) + nd] = lrelu(o);
    }
}

extern "C" void kernel_launch(void* const* d_in, const int* in_sizes, int n_in,
                              void* d_out, int out_size) {
    (void)in_sizes; (void)n_in; (void)out_size;
    const float* x    = (const float*)d_in[0];
    const float* W0   = (const float*)d_in[1];
    const float* b0   = (const float*)d_in[2];
    const float* W1   = (const float*)d_in[3];
    const float* b1   = (const float*)d_in[4];
    const float* W2   = (const float*)d_in[5];
    const float* b2   = (const float*)d_in[6];
    const float* Ws02 = (const float*)d_in[7];
    const float* bs02 = (const float*)d_in[8];
    const float* Ws13 = (const float*)d_in[9];
    const float* bs13 = (const float*)d_in[10];
    const float* Dw1  = (const float*)d_in[11];
    const float* Db1  = (const float*)d_in[12];
    const float* Dw2  = (const float*)d_in[13];
    const float* Db2  = (const float*)d_in[14];
    const float* Dw3  = (const float*)d_in[15];
    const float* Db3  = (const float*)d_in[16];
    float* out = (float*)d_out;

    float *h0 = nullptr, *h1 = nullptr;
    cudaGetSymbolAddress((void**)&h0, g_h0);
    cudaGetSymbolAddress((void**)&h1, g_h1);

    dim3 grid(4, 256), block(NTH);
    // Layer 0: h0 = DAN(x @ W0^T + b0, l=0)
    dan_layer_kernel<<<grid, block>>>(x, W0, b0, nullptr, nullptr, nullptr,
                                      Dw1, Db1, Dw2, Db2, Dw3, Db3, 0, 0, h0);
    // Layer 1: h1 = DAN(h0 @ W1^T + b1 + x @ Ws02^T + bs02, l=1)
    dan_layer_kernel<<<grid, block>>>(h0, W1, b1, x, Ws02, bs02,
                                      Dw1, Db1, Dw2, Db2, Dw3, Db3, 1, 1, h1);
    // Layer 2: out = DAN(h1 @ W2^T + b2 + h0 @ Ws13^T + bs13, l=2)
    dan_layer_kernel<<<grid, block>>>(h1, W2, b2, h0, Ws13, bs13,
                                      Dw1, Db1, Dw2, Db2, Dw3, Db3, 2, 1, out);
}

// round 3
// speedup vs baseline: 1.0003x; 1.0003x over previous
#include <cuda_runtime.h>

// ============================================================================
// NETWORK_OF_DANS — round 1 baseline
//
// 3 fused layer kernels. Each computes
//     pre = A1 @ B1^T + bias1 (+ A2 @ B2^T + bias2)      [512, 32768]
// as a 128x128x8-tiled SIMT fp32 GEMM using packed FFMA2 (fma.rn.f32x2),
// then applies the shared Simple_DAN (32 -> 15 -> 8 -> 1, leaky_relu 0.01)
// per node in the epilogue (via smem restage), emitting h [512, 1024].
// Pre-activations never touch HBM.
// ============================================================================

#define TILE_M 128
#define TILE_N 128
#define TILE_K 8
#define NTH 256

__device__ float g_h0[512 * 1024];
__device__ float g_h1[512 * 1024];

__device__ __forceinline__ float lrelu(float v) { return v > 0.0f ? v : 0.01f * v; }

__device__ __forceinline__ unsigned long long pack2(float lo, float hi) {
    unsigned long long r;
    asm("mov.b64 %0, {%1, %2};" : "=l"(r) : "f"(lo), "f"(hi));
    return r;
}
__device__ __forceinline__ void unpack2(unsigned long long v, float& lo, float& hi) {
    asm("mov.b64 {%0, %1}, %2;" : "=f"(lo), "=f"(hi) : "l"(v));
}
__device__ __forceinline__ void ffma2(unsigned long long& d, unsigned long long a,
                                      unsigned long long b) {
    asm("fma.rn.f32x2 %0, %1, %2, %3;" : "=l"(d) : "l"(a), "l"(b), "l"(d));
}

__global__ __launch_bounds__(NTH, 2)
void dan_layer_kernel(const float* __restrict__ A1, const float* __restrict__ B1,
                      const float* __restrict__ bias1,
                      const float* __restrict__ A2, const float* __restrict__ B2,
                      const float* __restrict__ bias2,
                      const float* __restrict__ Dw1, const float* __restrict__ Db1,
                      const float* __restrict__ Dw2, const float* __restrict__ Db2,
                      const float* __restrict__ Dw3, const float* __restrict__ Db3,
                      int layer_idx, int two_inputs,
                      float* __restrict__ out)
{
    // A tile stored as duplicated f32 pairs so FFMA2 broadcast operand is a
    // single LDS.64 (no per-k mov.b64 in the hot loop). Pads kill conflicts.
    __shared__ __align__(16) unsigned long long As2[TILE_K][130];
    __shared__ __align__(16) float Bs[TILE_K][132];
    __shared__ __align__(16) float ep[64][129];   // epilogue restage (row pad 1)
    __shared__ float sDw1[15 * 32];
    __shared__ float sDb1[15];
    __shared__ float sDw2[8 * 15];
    __shared__ float sDb2[8];
    __shared__ float sDw3[8];
    __shared__ float sDb3[1];

    const int tid = threadIdx.x;
    const int tx = tid & 15;     // n-dim thread coord (8 cols each)
    const int ty = tid >> 4;     // m-dim thread coord (8 rows each)
    const int bm = blockIdx.x * TILE_M;   // batch offset   (gridDim.x = 4)
    const int bn = blockIdx.y * TILE_N;   // out-col offset (gridDim.y = 256)

    // --- stage DAN weights (folded one-hot layer code into first-layer bias) ---
    for (int i = tid; i < 15 * 32; i += NTH)
        sDw1[i] = Dw1[(i >> 5) * 35 + (i & 31)];
    if (tid < 15) sDb1[tid] = Db1[tid] + Dw1[tid * 35 + 32 + layer_idx];
    if (tid >= 32 && tid < 152) sDw2[tid - 32] = Dw2[tid - 32];
    if (tid >= 160 && tid < 168) sDb2[tid - 160] = Db2[tid - 160];
    if (tid >= 168 && tid < 176) sDw3[tid - 168] = Dw3[tid - 168];
    if (tid == 176) sDb3[0] = Db3[0];

    // --- GEMM: acc[i][jj] = packed pair over columns (tx*8 + jj*2 + {0,1}) ---
    unsigned long long acc[8][4];
#pragma unroll
    for (int i = 0; i < 8; i++)
#pragma unroll
        for (int j = 0; j < 4; j++) acc[i][j] = 0ULL;

    const int ld_row = tid >> 1;        // 0..127 (row within tile, A and B)
    const int ld_k   = (tid & 1) * 4;   // 0 or 4 (k sub-offset, float4)

    const int total = two_inputs ? 256 : 128;  // K-tiles (K=1024 per input)

    float4 ra, rb;
    // prologue: load + store tile 0
    ra = *(const float4*)(A1 + (bm + ld_row) * 1024 + ld_k);
    rb = *(const float4*)(B1 + (bn + ld_row) * 1024 + ld_k);
    As2[ld_k + 0][ld_row] = pack2(ra.x, ra.x);
    As2[ld_k + 1][ld_row] = pack2(ra.y, ra.y);
    As2[ld_k + 2][ld_row] = pack2(ra.z, ra.z);
    As2[ld_k + 3][ld_row] = pack2(ra.w, ra.w);
    Bs[ld_k + 0][ld_row] = rb.x;
    Bs[ld_k + 1][ld_row] = rb.y;
    Bs[ld_k + 2][ld_row] = rb.z;
    Bs[ld_k + 3][ld_row] = rb.w;

    for (int t = 0; t < total; ++t) {
        __syncthreads();  // tile t visible in smem

        if (t + 1 < total) {  // prefetch next tile into registers
            const int tn = t + 1;
            const float* Ap = (tn < 128) ? A1 : A2;
            const float* Bp = (tn < 128) ? B1 : B2;
            const int k0 = (tn & 127) * TILE_K;
            ra = *(const float4*)(Ap + (bm + ld_row) * 1024 + k0 + ld_k);
            rb = *(const float4*)(Bp + (bn + ld_row) * 1024 + k0 + ld_k);
        }

#pragma unroll
        for (int k = 0; k < TILE_K; ++k) {
            unsigned long long ap[8];
            ulonglong2 a0 = *(const ulonglong2*)&As2[k][ty * 8 + 0];
            ulonglong2 a1 = *(const ulonglong2*)&As2[k][ty * 8 + 2];
            ulonglong2 a2 = *(const ulonglong2*)&As2[k][ty * 8 + 4];
            ulonglong2 a3 = *(const ulonglong2*)&As2[k][ty * 8 + 6];
            ap[0] = a0.x; ap[1] = a0.y; ap[2] = a1.x; ap[3] = a1.y;
            ap[4] = a2.x; ap[5] = a2.y; ap[6] = a3.x; ap[7] = a3.y;
            ulonglong2 b0 = *(const ulonglong2*)&Bs[k][tx * 8 + 0];
            ulonglong2 b1 = *(const ulonglong2*)&Bs[k][tx * 8 + 4];
            unsigned long long bp[4] = {b0.x, b0.y, b1.x, b1.y};
#pragma unroll
            for (int i = 0; i < 8; i++)
#pragma unroll
                for (int jj = 0; jj < 4; jj++)
                    ffma2(acc[i][jj], ap[i], bp[jj]);
        }

        __syncthreads();  // done reading tile t

        if (t + 1 < total) {  // commit prefetched tile
            As2[ld_k + 0][ld_row] = pack2(ra.x, ra.x);
            As2[ld_k + 1][ld_row] = pack2(ra.y, ra.y);
            As2[ld_k + 2][ld_row] = pack2(ra.z, ra.z);
            As2[ld_k + 3][ld_row] = pack2(ra.w, ra.w);
            Bs[ld_k + 0][ld_row] = rb.x;
            Bs[ld_k + 1][ld_row] = rb.y;
            Bs[ld_k + 2][ld_row] = rb.z;
            Bs[ld_k + 3][ld_row] = rb.w;
        }
    }

    // --- pre-activation bias for this thread's 8 columns ---
    float bcol[8];
#pragma unroll
    for (int j = 0; j < 8; j++) {
        const int ng = bn + tx * 8 + j;
        float s = bias1[ng];
        if (two_inputs) s += bias2[ng];
        bcol[j] = s;
    }

    // --- DAN epilogue: restage 64 rows x 128 cols at a time, then per-(row,node)
    //     threads run the 32->15->8->1 MLP. Row pad 129 => conflict-free reads. ---
    const int r  = tid & 63;   // row within half
    const int nd = tid >> 6;   // node within tile (TILE_N = 4 nodes x 32 ch)

    for (int h = 0; h < 2; ++h) {
        __syncthreads();
        if ((ty >> 3) == h) {
            const int tyl = (ty & 7) * 8;
#pragma unroll
            for (int i = 0; i < 8; i++)
#pragma unroll
                for (int jj = 0; jj < 4; jj++) {
                    float lo, hi;
                    unpack2(acc[i][jj], lo, hi);
                    ep[tyl + i][tx * 8 + jj * 2 + 0] = lo + bcol[jj * 2 + 0];
                    ep[tyl + i][tx * 8 + jj * 2 + 1] = hi + bcol[jj * 2 + 1];
                }
        }
        __syncthreads();

        float z[32];
#pragma unroll
        for (int c = 0; c < 32; c++) z[c] = ep[r][nd * 32 + c];

        float h1v[15];
#pragma unroll
        for (int u = 0; u < 15; u++) {
            float s = sDb1[u];
#pragma unroll
            for (int c = 0; c < 32; c++) s = fmaf(sDw1[u * 32 + c], z[c], s);
            h1v[u] = lrelu(s);
        }
        float o = sDb3[0];
#pragma unroll
        for (int v = 0; v < 8; v++) {
            float s = sDb2[v];
#pragma unroll
            for (int u = 0; u < 15; u++) s = fmaf(sDw2[v * 15 + u], h1v[u], s);
            o = fmaf(sDw3[v], lrelu(s), o);
        }
        out[(bm + h * 64 + r) * 1024 + (bn >> 5) + nd] = lrelu(o);
    }
}

extern "C" void kernel_launch(void* const* d_in, const int* in_sizes, int n_in,
                              void* d_out, int out_size) {
    (void)in_sizes; (void)n_in; (void)out_size;
    const float* x    = (const float*)d_in[0];
    const float* W0   = (const float*)d_in[1];
    const float* b0   = (const float*)d_in[2];
    const float* W1   = (const float*)d_in[3];
    const float* b1   = (const float*)d_in[4];
    const float* W2   = (const float*)d_in[5];
    const float* b2   = (const float*)d_in[6];
    const float* Ws02 = (const float*)d_in[7];
    const float* bs02 = (const float*)d_in[8];
    const float* Ws13 = (const float*)d_in[9];
    const float* bs13 = (const float*)d_in[10];
    const float* Dw1  = (const float*)d_in[11];
    const float* Db1  = (const float*)d_in[12];
    const float* Dw2  = (const float*)d_in[13];
    const float* Db2  = (const float*)d_in[14];
    const float* Dw3  = (const float*)d_in[15];
    const float* Db3  = (const float*)d_in[16];
    float* out = (float*)d_out;

    float *h0 = nullptr, *h1 = nullptr;
    cudaGetSymbolAddress((void**)&h0, g_h0);
    cudaGetSymbolAddress((void**)&h1, g_h1);

    dim3 grid(4, 256), block(NTH);
    // Layer 0: h0 = DAN(x @ W0^T + b0, l=0)
    dan_layer_kernel<<<grid, block>>>(x, W0, b0, nullptr, nullptr, nullptr,
                                      Dw1, Db1, Dw2, Db2, Dw3, Db3, 0, 0, h0);
    // Layer 1: h1 = DAN(h0 @ W1^T + b1 + x @ Ws02^T + bs02, l=1)
    dan_layer_kernel<<<grid, block>>>(h0, W1, b1, x, Ws02, bs02,
                                      Dw1, Db1, Dw2, Db2, Dw3, Db3, 1, 1, h1);
    // Layer 2: out = DAN(h1 @ W2^T + b2 + h0 @ Ws13^T + bs13, l=2)
    dan_layer_kernel<<<grid, block>>>(h1, W2, b2, h0, Ws13, bs13,
                                      Dw1, Db1, Dw2, Db2, Dw3, Db3, 2, 1, out);
}

// round 5
// speedup vs baseline: 3.3495x; 3.3484x over previous
#include <cuda_runtime.h>
#include <cuda_bf16.h>
#include <cstdint>

// ============================================================================
// NETWORK_OF_DANS — round 4: split-bf16 HMMA (mma.sync) GEMM + fused DAN
//
// tcgen05 is rejected by this build's compute_103 virtual arch, so the tensor
// path is sm_80-class mma.sync.m16n8k16.bf16 (legal baseline PTX), 3-term
// split-bf16 for fp32-grade accuracy:
//     A@B^T ~= Ah@Bh^T + Ah@Bl^T + Al@Bh^T      (fp32 accumulate)
// Layers are K-concatenated so each layer is ONE GEMM (K = 1024 / 2048).
// DAN (32->15->8->1, lrelu 0.01) runs in the epilogue from registers/smem.
// ============================================================================

#define NTH 256
#define BM 128
#define BN 128
#define BK 64                 // k-chunk in elements (128 B per row)

// ---------------- scratch (bf16 bit patterns as ushort) ---------------------
__device__ unsigned short g_A0h[512 * 1024],  g_A0l[512 * 1024];
__device__ unsigned short g_A1h[512 * 2048],  g_A1l[512 * 2048];
__device__ unsigned short g_A2h[512 * 2048],  g_A2l[512 * 2048];
__device__ unsigned short g_B0h[32768 * 1024], g_B0l[32768 * 1024];
__device__ unsigned short g_B1h[32768 * 2048], g_B1l[32768 * 2048];
__device__ unsigned short g_B2h[32768 * 2048], g_B2l[32768 * 2048];

// ---------------- smem layout (dynamic) -------------------------------------
#define T_AHI 0
#define T_ALO 16384
#define T_BHI 32768
#define T_BLO 49152
#define STG_SZ 65536          // 4 tiles x 128x64 bf16
#define SM_BIAS (3 * STG_SZ)              // 196608: 128 floats
#define SM_DW1  (SM_BIAS + 512)           // 480 floats
#define SM_DB1  (SM_DW1 + 1920)           // 15
#define SM_DW2  (SM_DB1 + 64)             // 120
#define SM_DB2  (SM_DW2 + 480)            // 8
#define SM_DW3  (SM_DB2 + 32)             // 8
#define SM_DB3  (SM_DW3 + 32)             // 1
#define SMEM_TOTAL (SM_DB3 + 16)          // ~199.7 KB

#define SWZ(o) ((o) ^ (((o) >> 3) & 0x70))

__device__ __forceinline__ uint32_t smem_u32(const void* p) {
    uint32_t a;
    asm("{ .reg .u64 t; cvta.to.shared.u64 t, %1; cvt.u32.u64 %0, t; }"
        : "=r"(a) : "l"(p));
    return a;
}
__device__ __forceinline__ float lrelu(float v) { return v > 0.0f ? v : 0.01f * v; }

__device__ __forceinline__ void ldsm4(uint32_t* r, uint32_t a) {
    asm volatile("ldmatrix.sync.aligned.m8n8.x4.shared.b16 {%0,%1,%2,%3}, [%4];"
                 : "=r"(r[0]), "=r"(r[1]), "=r"(r[2]), "=r"(r[3]) : "r"(a));
}
__device__ __forceinline__ void mma16816(float* d, const uint32_t* a,
                                         const uint32_t* b) {
    asm volatile(
        "mma.sync.aligned.m16n8k16.row.col.f32.bf16.bf16.f32 "
        "{%0,%1,%2,%3}, {%4,%5,%6,%7}, {%8,%9}, {%0,%1,%2,%3};"
        : "+f"(d[0]), "+f"(d[1]), "+f"(d[2]), "+f"(d[3])
        : "r"(a[0]), "r"(a[1]), "r"(a[2]), "r"(a[3]), "r"(b[0]), "r"(b[1]));
}
__device__ __forceinline__ void cpa16(uint32_t s, const void* g) {
    asm volatile("cp.async.cg.shared.global [%0], [%1], 16;" :: "r"(s), "l"(g));
}
#define CP_COMMIT() asm volatile("cp.async.commit_group;" ::: "memory")
#define CP_WAIT(n)  asm volatile("cp.async.wait_group %0;" :: "n"(n) : "memory")

// ---------------------------------------------------------------------------
// Conversion: f32 [rows,1024] -> bf16 hi (truncated) / lo (RN of residual)
// ---------------------------------------------------------------------------
__global__ __launch_bounds__(256) void conv_split(
    const float* __restrict__ src, unsigned short* __restrict__ dh,
    unsigned short* __restrict__ dl, int dst_ld, int dst_off, int total8)
{
    int idx = blockIdx.x * 256 + threadIdx.x;
    if (idx >= total8) return;
    int r = idx >> 7, c = idx & 127;
    const float4* s = (const float4*)(src + (size_t)r * 1024 + c * 8);
    float4 v0 = s[0], v1 = s[1];

    uint32_t b[8] = {__float_as_uint(v0.x), __float_as_uint(v0.y),
                     __float_as_uint(v0.z), __float_as_uint(v0.w),
                     __float_as_uint(v1.x), __float_as_uint(v1.y),
                     __float_as_uint(v1.z), __float_as_uint(v1.w)};
    float f[8] = {v0.x, v0.y, v0.z, v0.w, v1.x, v1.y, v1.z, v1.w};

    uint4 H;
    H.x = __byte_perm(b[0], b[1], 0x7632);
    H.y = __byte_perm(b[2], b[3], 0x7632);
    H.z = __byte_perm(b[4], b[5], 0x7632);
    H.w = __byte_perm(b[6], b[7], 0x7632);

    float lo[8];
#pragma unroll
    for (int i = 0; i < 8; i++)
        lo[i] = f[i] - __uint_as_float(b[i] & 0xFFFF0000u);

    __nv_bfloat162 l0 = __floats2bfloat162_rn(lo[0], lo[1]);
    __nv_bfloat162 l1 = __floats2bfloat162_rn(lo[2], lo[3]);
    __nv_bfloat162 l2 = __floats2bfloat162_rn(lo[4], lo[5]);
    __nv_bfloat162 l3 = __floats2bfloat162_rn(lo[6], lo[7]);
    uint4 L;
    L.x = *(uint32_t*)&l0; L.y = *(uint32_t*)&l1;
    L.z = *(uint32_t*)&l2; L.w = *(uint32_t*)&l3;

    size_t d = (size_t)r * dst_ld + dst_off + c * 8;
    *(uint4*)(dh + d) = H;
    *(uint4*)(dl + d) = L;
}

// ---------------------------------------------------------------------------
// Fused split-bf16 HMMA GEMM + DAN epilogue.
// Grid (4, 256): bm = bx*128, bn = by*128. 256 threads = 8 warps (2m x 4n),
// warp tile 64x32 (one DAN node wide).
// ---------------------------------------------------------------------------
__global__ __launch_bounds__(NTH, 1) void dan_gemm_kernel(
    const unsigned short* __restrict__ Ah, const unsigned short* __restrict__ Al,
    const unsigned short* __restrict__ Bh, const unsigned short* __restrict__ Bl,
    int ldK, int nchunks,
    const float* __restrict__ bias1, const float* __restrict__ bias2,
    const float* __restrict__ Dw1, const float* __restrict__ Db1,
    const float* __restrict__ Dw2, const float* __restrict__ Db2,
    const float* __restrict__ Dw3, const float* __restrict__ Db3,
    int layer_idx, int mode,                       // 0: fp32 out; 1: bf16 hi/lo
    float* __restrict__ outf,
    unsigned short* __restrict__ oh1, unsigned short* __restrict__ ol1,
    unsigned short* __restrict__ oh2, unsigned short* __restrict__ ol2)
{
    extern __shared__ __align__(1024) char smem[];
    const uint32_t sb = smem_u32(smem);
    const int tid = threadIdx.x;
    const int wid = tid >> 5, lane = tid & 31;
    const int wm = wid >> 2, wn = wid & 3;       // 2 x 4 warp grid
    const int bm = blockIdx.x * BM, bn = blockIdx.y * BN;

    // ---- stage DAN weights + bias ----
    float* sDw1 = (float*)(smem + SM_DW1);
    float* sDb1 = (float*)(smem + SM_DB1);
    float* sDw2 = (float*)(smem + SM_DW2);
    float* sDb2 = (float*)(smem + SM_DB2);
    float* sDw3 = (float*)(smem + SM_DW3);
    float* sDb3 = (float*)(smem + SM_DB3);
    float* sBias = (float*)(smem + SM_BIAS);
    for (int i = tid; i < 15 * 32; i += NTH) sDw1[i] = Dw1[(i >> 5) * 35 + (i & 31)];
    if (tid < 15) sDb1[tid] = Db1[tid] + Dw1[tid * 35 + 32 + layer_idx];
    if (tid >= 32 && tid < 152) sDw2[tid - 32] = Dw2[tid - 32];
    if (tid >= 160 && tid < 168) sDb2[tid - 160] = Db2[tid - 160];
    if (tid >= 168 && tid < 176) sDw3[tid - 168] = Dw3[tid - 168];
    if (tid == 176) sDb3[0] = Db3[0];
    if (tid < 128) sBias[tid] = bias1[bn + tid] + (bias2 ? bias2[bn + tid] : 0.0f);

    // ---- loader: chunk t -> stage s (16B cp.async x 16 per thread) ----
    const int lrow = tid >> 3;          // 0..31 base row step of 32? no: ci layout below
    (void)lrow;
#define LOAD_STAGE(t, s) do {                                                   \
        const uint32_t stg_ = sb + (s) * STG_SZ;                                \
        const int k0_ = (t) * BK;                                               \
        _Pragma("unroll")                                                       \
        for (int j = 0; j < 4; ++j) {                                           \
            int ci = tid + j * NTH;            /* 0..1023 */                    \
            int row = ci >> 3, ch = ci & 7;                                     \
            uint32_t so = SWZ(row * 128 + ch * 16);                             \
            size_t ga = (size_t)(bm + row) * ldK + k0_ + ch * 8;                \
            size_t gb = (size_t)(bn + row) * ldK + k0_ + ch * 8;                \
            cpa16(stg_ + T_AHI + so, Ah + ga);                                  \
            cpa16(stg_ + T_ALO + so, Al + ga);                                  \
            cpa16(stg_ + T_BHI + so, Bh + gb);                                  \
            cpa16(stg_ + T_BLO + so, Bl + gb);                                  \
        }                                                                       \
    } while (0)

    // ---- accumulators ----
    float acc[4][4][4];
#pragma unroll
    for (int i = 0; i < 4; i++)
#pragma unroll
        for (int j = 0; j < 4; j++)
#pragma unroll
            for (int k = 0; k < 4; k++) acc[i][j][k] = 0.0f;

    // per-lane ldmatrix row bases (byte offsets within a 128x64 tile)
    const int rowA = wm * 64 + (lane & 15);
    const int rowB = wn * 32 + ((lane >> 4) & 1) * 8 + (lane & 7);
    const uint32_t baseA = rowA * 128;
    const uint32_t baseB = rowB * 128;
    const int xorv = lane & 7;
    const int chA = lane >> 4;          // 0/1
    const int chB = (lane >> 3) & 1;    // 0/1

    // ---- 3-stage pipeline ----
    LOAD_STAGE(0, 0); CP_COMMIT();
    LOAD_STAGE(1, 1); CP_COMMIT();

    for (int t = 0; t < nchunks; ++t) {
        CP_WAIT(1);
        __syncthreads();
        const int tn = t + 2;
        if (tn < nchunks) { int sl = tn % 3; LOAD_STAGE(tn, sl); }
        CP_COMMIT();

        const uint32_t stg = sb + (t % 3) * STG_SZ;
#pragma unroll
        for (int ks = 0; ks < 4; ++ks) {
            const uint32_t cA = (uint32_t)(((ks * 2 + chA) ^ xorv) << 4);
            const uint32_t cB = (uint32_t)(((ks * 2 + chB) ^ xorv) << 4);
            uint32_t aH[4][4], aL[4][4], bH[2][4], bL[2][4];
#pragma unroll
            for (int mt = 0; mt < 4; ++mt) {
                ldsm4(aH[mt], stg + T_AHI + baseA + mt * 2048 + cA);
                ldsm4(aL[mt], stg + T_ALO + baseA + mt * 2048 + cA);
            }
#pragma unroll
            for (int p = 0; p < 2; ++p) {
                ldsm4(bH[p], stg + T_BHI + baseB + p * 2048 + cB);
                ldsm4(bL[p], stg + T_BLO + baseB + p * 2048 + cB);
            }
#pragma unroll
            for (int mt = 0; mt < 4; ++mt)
#pragma unroll
                for (int nt = 0; nt < 4; ++nt) {
                    const uint32_t* bh = &bH[nt >> 1][(nt & 1) * 2];
                    const uint32_t* bl = &bL[nt >> 1][(nt & 1) * 2];
                    mma16816(acc[mt][nt], aH[mt], bh);
                    mma16816(acc[mt][nt], aH[mt], bl);
                    mma16816(acc[mt][nt], aL[mt], bh);
                }
        }
    }

    // ---- epilogue: stage warp tile (+bias), then per-lane DAN ----
    CP_WAIT(0);
    __syncthreads();

    float* ep = (float*)(smem + wid * 8448);   // [64][33] per warp
    const int r0 = lane >> 2, c0 = (lane & 3) * 2;
#pragma unroll
    for (int mt = 0; mt < 4; ++mt)
#pragma unroll
        for (int nt = 0; nt < 4; ++nt) {
            int rr = mt * 16 + r0, cc = nt * 8 + c0;
            float bx0 = sBias[wn * 32 + cc], bx1 = sBias[wn * 32 + cc + 1];
            ep[rr * 33 + cc]           = acc[mt][nt][0] + bx0;
            ep[rr * 33 + cc + 1]       = acc[mt][nt][1] + bx1;
            ep[(rr + 8) * 33 + cc]     = acc[mt][nt][2] + bx0;
            ep[(rr + 8) * 33 + cc + 1] = acc[mt][nt][3] + bx1;
        }
    __syncwarp();

    const int gnode = (bn >> 5) + wn;
#pragma unroll
    for (int rr = 0; rr < 2; ++rr) {
        const int r = lane * 2 + rr;
        const float* zr = ep + r * 33;
        float h1v[15];
#pragma unroll
        for (int u = 0; u < 15; ++u) {
            float s = sDb1[u];
#pragma unroll
            for (int c = 0; c < 32; ++c) s = fmaf(sDw1[u * 32 + c], zr[c], s);
            h1v[u] = lrelu(s);
        }
        float o = sDb3[0];
#pragma unroll
        for (int v = 0; v < 8; ++v) {
            float s = sDb2[v];
#pragma unroll
            for (int u = 0; u < 15; ++u) s = fmaf(sDw2[v * 15 + u], h1v[u], s);
            o = fmaf(sDw3[v], lrelu(s), o);
        }
        o = lrelu(o);

        const int grow = bm + wm * 64 + r;
        if (mode == 0) {
            outf[(size_t)grow * 1024 + gnode] = o;
        } else {
            uint32_t ob = __float_as_uint(o);
            unsigned short hb = (unsigned short)(ob >> 16);
            float lof = o - __uint_as_float(ob & 0xFFFF0000u);
            __nv_bfloat16 lb16 = __float2bfloat16(lof);
            unsigned short lb = *(unsigned short*)&lb16;
            size_t di = (size_t)grow * 2048 + gnode;
            oh1[di] = hb; ol1[di] = lb;
            if (oh2) { oh2[di + 1024] = hb; ol2[di + 1024] = lb; }
        }
    }
#undef LOAD_STAGE
}

// ---------------------------------------------------------------------------
extern "C" void kernel_launch(void* const* d_in, const int* in_sizes, int n_in,
                              void* d_out, int out_size) {
    (void)in_sizes; (void)n_in; (void)out_size;
    const float* x    = (const float*)d_in[0];
    const float* W0   = (const float*)d_in[1];
    const float* b0   = (const float*)d_in[2];
    const float* W1   = (const float*)d_in[3];
    const float* b1   = (const float*)d_in[4];
    const float* W2   = (const float*)d_in[5];
    const float* b2   = (const float*)d_in[6];
    const float* Ws02 = (const float*)d_in[7];
    const float* bs02 = (const float*)d_in[8];
    const float* Ws13 = (const float*)d_in[9];
    const float* bs13 = (const float*)d_in[10];
    const float* Dw1  = (const float*)d_in[11];
    const float* Db1  = (const float*)d_in[12];
    const float* Dw2  = (const float*)d_in[13];
    const float* Db2  = (const float*)d_in[14];
    const float* Dw3  = (const float*)d_in[15];
    const float* Db3  = (const float*)d_in[16];
    float* out = (float*)d_out;

    unsigned short *A0h, *A0l, *A1h, *A1l, *A2h, *A2l;
    unsigned short *B0h, *B0l, *B1h, *B1l, *B2h, *B2l;
    cudaGetSymbolAddress((void**)&A0h, g_A0h); cudaGetSymbolAddress((void**)&A0l, g_A0l);
    cudaGetSymbolAddress((void**)&A1h, g_A1h); cudaGetSymbolAddress((void**)&A1l, g_A1l);
    cudaGetSymbolAddress((void**)&A2h, g_A2h); cudaGetSymbolAddress((void**)&A2l, g_A2l);
    cudaGetSymbolAddress((void**)&B0h, g_B0h); cudaGetSymbolAddress((void**)&B0l, g_B0l);
    cudaGetSymbolAddress((void**)&B1h, g_B1h); cudaGetSymbolAddress((void**)&B1l, g_B1l);
    cudaGetSymbolAddress((void**)&B2h, g_B2h); cudaGetSymbolAddress((void**)&B2l, g_B2l);

    cudaFuncSetAttribute(dan_gemm_kernel,
                         cudaFuncAttributeMaxDynamicSharedMemorySize, SMEM_TOTAL);

    const int W8 = 32768 * 128;
    const int X8 = 512 * 128;

    conv_split<<<(X8 + 255) / 256, 256>>>(x, A0h, A0l, 1024, 0, X8);
    conv_split<<<(X8 + 255) / 256, 256>>>(x, A1h, A1l, 2048, 1024, X8);
    conv_split<<<(W8 + 255) / 256, 256>>>(W0,   B0h, B0l, 1024, 0,    W8);
    conv_split<<<(W8 + 255) / 256, 256>>>(W1,   B1h, B1l, 2048, 0,    W8);
    conv_split<<<(W8 + 255) / 256, 256>>>(Ws02, B1h, B1l, 2048, 1024, W8);
    conv_split<<<(W8 + 255) / 256, 256>>>(W2,   B2h, B2l, 2048, 0,    W8);
    conv_split<<<(W8 + 255) / 256, 256>>>(Ws13, B2h, B2l, 2048, 1024, W8);

    dim3 grid(4, 256), block(NTH);
    // layer 0: h0 = DAN(x @ W0^T + b0) -> A1cat[:, :1024], A2cat[:, 1024:]
    dan_gemm_kernel<<<grid, block, SMEM_TOTAL>>>(
        A0h, A0l, B0h, B0l, 1024, 16, b0, nullptr,
        Dw1, Db1, Dw2, Db2, Dw3, Db3, 0, 1,
        nullptr, A1h, A1l, A2h, A2l);
    // layer 1: h1 = DAN([h0|x] @ [W1|Ws02]^T + b1 + bs02) -> A2cat[:, :1024]
    dan_gemm_kernel<<<grid, block, SMEM_TOTAL>>>(
        A1h, A1l, B1h, B1l, 2048, 32, b1, bs02,
        Dw1, Db1, Dw2, Db2, Dw3, Db3, 1, 1,
        nullptr, A2h, A2l, nullptr, nullptr);
    // layer 2: out = DAN([h1|h0] @ [W2|Ws13]^T + b2 + bs13)
    dan_gemm_kernel<<<grid, block, SMEM_TOTAL>>>(
        A2h, A2l, B2h, B2l, 2048, 32, b2, bs13,
        Dw1, Db1, Dw2, Db2, Dw3, Db3, 2, 0,
        out, nullptr, nullptr, nullptr, nullptr);
}

// round 6
// speedup vs baseline: 3.3525x; 1.0009x over previous
#include <cuda_runtime.h>
#include <cuda_bf16.h>
#include <cstdint>

// ============================================================================
// NETWORK_OF_DANS — round 4: split-bf16 HMMA (mma.sync) GEMM + fused DAN
//
// tcgen05 is rejected by this build's compute_103 virtual arch, so the tensor
// path is sm_80-class mma.sync.m16n8k16.bf16 (legal baseline PTX), 3-term
// split-bf16 for fp32-grade accuracy:
//     A@B^T ~= Ah@Bh^T + Ah@Bl^T + Al@Bh^T      (fp32 accumulate)
// Layers are K-concatenated so each layer is ONE GEMM (K = 1024 / 2048).
// DAN (32->15->8->1, lrelu 0.01) runs in the epilogue from registers/smem.
// ============================================================================

#define NTH 256
#define BM 128
#define BN 128
#define BK 64                 // k-chunk in elements (128 B per row)

// ---------------- scratch (bf16 bit patterns as ushort) ---------------------
__device__ unsigned short g_A0h[512 * 1024],  g_A0l[512 * 1024];
__device__ unsigned short g_A1h[512 * 2048],  g_A1l[512 * 2048];
__device__ unsigned short g_A2h[512 * 2048],  g_A2l[512 * 2048];
__device__ unsigned short g_B0h[32768 * 1024], g_B0l[32768 * 1024];
__device__ unsigned short g_B1h[32768 * 2048], g_B1l[32768 * 2048];
__device__ unsigned short g_B2h[32768 * 2048], g_B2l[32768 * 2048];

// ---------------- smem layout (dynamic) -------------------------------------
#define T_AHI 0
#define T_ALO 16384
#define T_BHI 32768
#define T_BLO 49152
#define STG_SZ 65536          // 4 tiles x 128x64 bf16
#define SM_BIAS (3 * STG_SZ)              // 196608: 128 floats
#define SM_DW1  (SM_BIAS + 512)           // 480 floats
#define SM_DB1  (SM_DW1 + 1920)           // 15
#define SM_DW2  (SM_DB1 + 64)             // 120
#define SM_DB2  (SM_DW2 + 480)            // 8
#define SM_DW3  (SM_DB2 + 32)             // 8
#define SM_DB3  (SM_DW3 + 32)             // 1
#define SMEM_TOTAL (SM_DB3 + 16)          // ~199.7 KB

#define SWZ(o) ((o) ^ (((o) >> 3) & 0x70))

__device__ __forceinline__ uint32_t smem_u32(const void* p) {
    uint32_t a;
    asm("{ .reg .u64 t; cvta.to.shared.u64 t, %1; cvt.u32.u64 %0, t; }"
        : "=r"(a) : "l"(p));
    return a;
}
__device__ __forceinline__ float lrelu(float v) { return v > 0.0f ? v : 0.01f * v; }

__device__ __forceinline__ void ldsm4(uint32_t* r, uint32_t a) {
    asm volatile("ldmatrix.sync.aligned.m8n8.x4.shared.b16 {%0,%1,%2,%3}, [%4];"
                 : "=r"(r[0]), "=r"(r[1]), "=r"(r[2]), "=r"(r[3]) : "r"(a));
}
__device__ __forceinline__ void mma16816(float* d, const uint32_t* a,
                                         const uint32_t* b) {
    asm volatile(
        "mma.sync.aligned.m16n8k16.row.col.f32.bf16.bf16.f32 "
        "{%0,%1,%2,%3}, {%4,%5,%6,%7}, {%8,%9}, {%0,%1,%2,%3};"
        : "+f"(d[0]), "+f"(d[1]), "+f"(d[2]), "+f"(d[3])
        : "r"(a[0]), "r"(a[1]), "r"(a[2]), "r"(a[3]), "r"(b[0]), "r"(b[1]));
}
__device__ __forceinline__ void cpa16(uint32_t s, const void* g) {
    asm volatile("cp.async.cg.shared.global [%0], [%1], 16;" :: "r"(s), "l"(g));
}
#define CP_COMMIT() asm volatile("cp.async.commit_group;" ::: "memory")
#define CP_WAIT(n)  asm volatile("cp.async.wait_group %0;" :: "n"(n) : "memory")

// ---------------------------------------------------------------------------
// Conversion: f32 [rows,1024] -> bf16 hi (truncated) / lo (RN of residual)
// ---------------------------------------------------------------------------
__global__ __launch_bounds__(256) void conv_split(
    const float* __restrict__ src, unsigned short* __restrict__ dh,
    unsigned short* __restrict__ dl, int dst_ld, int dst_off, int total8)
{
    int idx = blockIdx.x * 256 + threadIdx.x;
    if (idx >= total8) return;
    int r = idx >> 7, c = idx & 127;
    const float4* s = (const float4*)(src + (size_t)r * 1024 + c * 8);
    float4 v0 = s[0], v1 = s[1];

    uint32_t b[8] = {__float_as_uint(v0.x), __float_as_uint(v0.y),
                     __float_as_uint(v0.z), __float_as_uint(v0.w),
                     __float_as_uint(v1.x), __float_as_uint(v1.y),
                     __float_as_uint(v1.z), __float_as_uint(v1.w)};
    float f[8] = {v0.x, v0.y, v0.z, v0.w, v1.x, v1.y, v1.z, v1.w};

    uint4 H;
    H.x = __byte_perm(b[0], b[1], 0x7632);
    H.y = __byte_perm(b[2], b[3], 0x7632);
    H.z = __byte_perm(b[4], b[5], 0x7632);
    H.w = __byte_perm(b[6], b[7], 0x7632);

    float lo[8];
#pragma unroll
    for (int i = 0; i < 8; i++)
        lo[i] = f[i] - __uint_as_float(b[i] & 0xFFFF0000u);

    __nv_bfloat162 l0 = __floats2bfloat162_rn(lo[0], lo[1]);
    __nv_bfloat162 l1 = __floats2bfloat162_rn(lo[2], lo[3]);
    __nv_bfloat162 l2 = __floats2bfloat162_rn(lo[4], lo[5]);
    __nv_bfloat162 l3 = __floats2bfloat162_rn(lo[6], lo[7]);
    uint4 L;
    L.x = *(uint32_t*)&l0; L.y = *(uint32_t*)&l1;
    L.z = *(uint32_t*)&l2; L.w = *(uint32_t*)&l3;

    size_t d = (size_t)r * dst_ld + dst_off + c * 8;
    *(uint4*)(dh + d) = H;
    *(uint4*)(dl + d) = L;
}

// ---------------------------------------------------------------------------
// Fused split-bf16 HMMA GEMM + DAN epilogue.
// Grid (4, 256): bm = bx*128, bn = by*128. 256 threads = 8 warps (2m x 4n),
// warp tile 64x32 (one DAN node wide).
// ---------------------------------------------------------------------------
__global__ __launch_bounds__(NTH, 1) void dan_gemm_kernel(
    const unsigned short* __restrict__ Ah, const unsigned short* __restrict__ Al,
    const unsigned short* __restrict__ Bh, const unsigned short* __restrict__ Bl,
    int ldK, int nchunks,
    const float* __restrict__ bias1, const float* __restrict__ bias2,
    const float* __restrict__ Dw1, const float* __restrict__ Db1,
    const float* __restrict__ Dw2, const float* __restrict__ Db2,
    const float* __restrict__ Dw3, const float* __restrict__ Db3,
    int layer_idx, int mode,                       // 0: fp32 out; 1: bf16 hi/lo
    float* __restrict__ outf,
    unsigned short* __restrict__ oh1, unsigned short* __restrict__ ol1,
    unsigned short* __restrict__ oh2, unsigned short* __restrict__ ol2)
{
    extern __shared__ __align__(1024) char smem[];
    const uint32_t sb = smem_u32(smem);
    const int tid = threadIdx.x;
    const int wid = tid >> 5, lane = tid & 31;
    const int wm = wid >> 2, wn = wid & 3;       // 2 x 4 warp grid
    const int bm = blockIdx.x * BM, bn = blockIdx.y * BN;

    // ---- stage DAN weights + bias ----
    float* sDw1 = (float*)(smem + SM_DW1);
    float* sDb1 = (float*)(smem + SM_DB1);
    float* sDw2 = (float*)(smem + SM_DW2);
    float* sDb2 = (float*)(smem + SM_DB2);
    float* sDw3 = (float*)(smem + SM_DW3);
    float* sDb3 = (float*)(smem + SM_DB3);
    float* sBias = (float*)(smem + SM_BIAS);
    for (int i = tid; i < 15 * 32; i += NTH) sDw1[i] = Dw1[(i >> 5) * 35 + (i & 31)];
    if (tid < 15) sDb1[tid] = Db1[tid] + Dw1[tid * 35 + 32 + layer_idx];
    if (tid >= 32 && tid < 152) sDw2[tid - 32] = Dw2[tid - 32];
    if (tid >= 160 && tid < 168) sDb2[tid - 160] = Db2[tid - 160];
    if (tid >= 168 && tid < 176) sDw3[tid - 168] = Dw3[tid - 168];
    if (tid == 176) sDb3[0] = Db3[0];
    if (tid < 128) sBias[tid] = bias1[bn + tid] + (bias2 ? bias2[bn + tid] : 0.0f);

    // ---- loader: chunk t -> stage s (16B cp.async x 16 per thread) ----
    const int lrow = tid >> 3;          // 0..31 base row step of 32? no: ci layout below
    (void)lrow;
#define LOAD_STAGE(t, s) do {                                                   \
        const uint32_t stg_ = sb + (s) * STG_SZ;                                \
        const int k0_ = (t) * BK;                                               \
        _Pragma("unroll")                                                       \
        for (int j = 0; j < 4; ++j) {                                           \
            int ci = tid + j * NTH;            /* 0..1023 */                    \
            int row = ci >> 3, ch = ci & 7;                                     \
            uint32_t so = SWZ(row * 128 + ch * 16);                             \
            size_t ga = (size_t)(bm + row) * ldK + k0_ + ch * 8;                \
            size_t gb = (size_t)(bn + row) * ldK + k0_ + ch * 8;                \
            cpa16(stg_ + T_AHI + so, Ah + ga);                                  \
            cpa16(stg_ + T_ALO + so, Al + ga);                                  \
            cpa16(stg_ + T_BHI + so, Bh + gb);                                  \
            cpa16(stg_ + T_BLO + so, Bl + gb);                                  \
        }                                                                       \
    } while (0)

    // ---- accumulators ----
    float acc[4][4][4];
#pragma unroll
    for (int i = 0; i < 4; i++)
#pragma unroll
        for (int j = 0; j < 4; j++)
#pragma unroll
            for (int k = 0; k < 4; k++) acc[i][j][k] = 0.0f;

    // per-lane ldmatrix row bases (byte offsets within a 128x64 tile)
    const int rowA = wm * 64 + (lane & 15);
    const int rowB = wn * 32 + ((lane >> 4) & 1) * 8 + (lane & 7);
    const uint32_t baseA = rowA * 128;
    const uint32_t baseB = rowB * 128;
    const int xorv = lane & 7;
    const int chA = lane >> 4;          // 0/1
    const int chB = (lane >> 3) & 1;    // 0/1

    // ---- 3-stage pipeline ----
    LOAD_STAGE(0, 0); CP_COMMIT();
    LOAD_STAGE(1, 1); CP_COMMIT();

    for (int t = 0; t < nchunks; ++t) {
        CP_WAIT(1);
        __syncthreads();
        const int tn = t + 2;
        if (tn < nchunks) { int sl = tn % 3; LOAD_STAGE(tn, sl); }
        CP_COMMIT();

        const uint32_t stg = sb + (t % 3) * STG_SZ;
#pragma unroll
        for (int ks = 0; ks < 4; ++ks) {
            const uint32_t cA = (uint32_t)(((ks * 2 + chA) ^ xorv) << 4);
            const uint32_t cB = (uint32_t)(((ks * 2 + chB) ^ xorv) << 4);
            uint32_t aH[4][4], aL[4][4], bH[2][4], bL[2][4];
#pragma unroll
            for (int mt = 0; mt < 4; ++mt) {
                ldsm4(aH[mt], stg + T_AHI + baseA + mt * 2048 + cA);
                ldsm4(aL[mt], stg + T_ALO + baseA + mt * 2048 + cA);
            }
#pragma unroll
            for (int p = 0; p < 2; ++p) {
                ldsm4(bH[p], stg + T_BHI + baseB + p * 2048 + cB);
                ldsm4(bL[p], stg + T_BLO + baseB + p * 2048 + cB);
            }
#pragma unroll
            for (int mt = 0; mt < 4; ++mt)
#pragma unroll
                for (int nt = 0; nt < 4; ++nt) {
                    const uint32_t* bh = &bH[nt >> 1][(nt & 1) * 2];
                    const uint32_t* bl = &bL[nt >> 1][(nt & 1) * 2];
                    mma16816(acc[mt][nt], aH[mt], bh);
                    mma16816(acc[mt][nt], aH[mt], bl);
                    mma16816(acc[mt][nt], aL[mt], bh);
                }
        }
    }

    // ---- epilogue: stage warp tile (+bias), then per-lane DAN ----
    CP_WAIT(0);
    __syncthreads();

    float* ep = (float*)(smem + wid * 8448);   // [64][33] per warp
    const int r0 = lane >> 2, c0 = (lane & 3) * 2;
#pragma unroll
    for (int mt = 0; mt < 4; ++mt)
#pragma unroll
        for (int nt = 0; nt < 4; ++nt) {
            int rr = mt * 16 + r0, cc = nt * 8 + c0;
            float bx0 = sBias[wn * 32 + cc], bx1 = sBias[wn * 32 + cc + 1];
            ep[rr * 33 + cc]           = acc[mt][nt][0] + bx0;
            ep[rr * 33 + cc + 1]       = acc[mt][nt][1] + bx1;
            ep[(rr + 8) * 33 + cc]     = acc[mt][nt][2] + bx0;
            ep[(rr + 8) * 33 + cc + 1] = acc[mt][nt][3] + bx1;
        }
    __syncwarp();

    const int gnode = (bn >> 5) + wn;
#pragma unroll
    for (int rr = 0; rr < 2; ++rr) {
        const int r = lane * 2 + rr;
        const float* zr = ep + r * 33;
        float h1v[15];
#pragma unroll
        for (int u = 0; u < 15; ++u) {
            float s = sDb1[u];
#pragma unroll
            for (int c = 0; c < 32; ++c) s = fmaf(sDw1[u * 32 + c], zr[c], s);
            h1v[u] = lrelu(s);
        }
        float o = sDb3[0];
#pragma unroll
        for (int v = 0; v < 8; ++v) {
            float s = sDb2[v];
#pragma unroll
            for (int u = 0; u < 15; ++u) s = fmaf(sDw2[v * 15 + u], h1v[u], s);
            o = fmaf(sDw3[v], lrelu(s), o);
        }
        o = lrelu(o);

        const int grow = bm + wm * 64 + r;
        if (mode == 0) {
            outf[(size_t)grow * 1024 + gnode] = o;
        } else {
            uint32_t ob = __float_as_uint(o);
            unsigned short hb = (unsigned short)(ob >> 16);
            float lof = o - __uint_as_float(ob & 0xFFFF0000u);
            __nv_bfloat16 lb16 = __float2bfloat16(lof);
            unsigned short lb = *(unsigned short*)&lb16;
            size_t di = (size_t)grow * 2048 + gnode;
            oh1[di] = hb; ol1[di] = lb;
            if (oh2) { oh2[di + 1024] = hb; ol2[di + 1024] = lb; }
        }
    }
#undef LOAD_STAGE
}

// ---------------------------------------------------------------------------
extern "C" void kernel_launch(void* const* d_in, const int* in_sizes, int n_in,
                              void* d_out, int out_size) {
    (void)in_sizes; (void)n_in; (void)out_size;
    const float* x    = (const float*)d_in[0];
    const float* W0   = (const float*)d_in[1];
    const float* b0   = (const float*)d_in[2];
    const float* W1   = (const float*)d_in[3];
    const float* b1   = (const float*)d_in[4];
    const float* W2   = (const float*)d_in[5];
    const float* b2   = (const float*)d_in[6];
    const float* Ws02 = (const float*)d_in[7];
    const float* bs02 = (const float*)d_in[8];
    const float* Ws13 = (const float*)d_in[9];
    const float* bs13 = (const float*)d_in[10];
    const float* Dw1  = (const float*)d_in[11];
    const float* Db1  = (const float*)d_in[12];
    const float* Dw2  = (const float*)d_in[13];
    const float* Db2  = (const float*)d_in[14];
    const float* Dw3  = (const float*)d_in[15];
    const float* Db3  = (const float*)d_in[16];
    float* out = (float*)d_out;

    unsigned short *A0h, *A0l, *A1h, *A1l, *A2h, *A2l;
    unsigned short *B0h, *B0l, *B1h, *B1l, *B2h, *B2l;
    cudaGetSymbolAddress((void**)&A0h, g_A0h); cudaGetSymbolAddress((void**)&A0l, g_A0l);
    cudaGetSymbolAddress((void**)&A1h, g_A1h); cudaGetSymbolAddress((void**)&A1l, g_A1l);
    cudaGetSymbolAddress((void**)&A2h, g_A2h); cudaGetSymbolAddress((void**)&A2l, g_A2l);
    cudaGetSymbolAddress((void**)&B0h, g_B0h); cudaGetSymbolAddress((void**)&B0l, g_B0l);
    cudaGetSymbolAddress((void**)&B1h, g_B1h); cudaGetSymbolAddress((void**)&B1l, g_B1l);
    cudaGetSymbolAddress((void**)&B2h, g_B2h); cudaGetSymbolAddress((void**)&B2l, g_B2l);

    cudaFuncSetAttribute(dan_gemm_kernel,
                         cudaFuncAttributeMaxDynamicSharedMemorySize, SMEM_TOTAL);

    const int W8 = 32768 * 128;
    const int X8 = 512 * 128;

    conv_split<<<(X8 + 255) / 256, 256>>>(x, A0h, A0l, 1024, 0, X8);
    conv_split<<<(X8 + 255) / 256, 256>>>(x, A1h, A1l, 2048, 1024, X8);
    conv_split<<<(W8 + 255) / 256, 256>>>(W0,   B0h, B0l, 1024, 0,    W8);
    conv_split<<<(W8 + 255) / 256, 256>>>(W1,   B1h, B1l, 2048, 0,    W8);
    conv_split<<<(W8 + 255) / 256, 256>>>(Ws02, B1h, B1l, 2048, 1024, W8);
    conv_split<<<(W8 + 255) / 256, 256>>>(W2,   B2h, B2l, 2048, 0,    W8);
    conv_split<<<(W8 + 255) / 256, 256>>>(Ws13, B2h, B2l, 2048, 1024, W8);

    dim3 grid(4, 256), block(NTH);
    // layer 0: h0 = DAN(x @ W0^T + b0) -> A1cat[:, :1024], A2cat[:, 1024:]
    dan_gemm_kernel<<<grid, block, SMEM_TOTAL>>>(
        A0h, A0l, B0h, B0l, 1024, 16, b0, nullptr,
        Dw1, Db1, Dw2, Db2, Dw3, Db3, 0, 1,
        nullptr, A1h, A1l, A2h, A2l);
    // layer 1: h1 = DAN([h0|x] @ [W1|Ws02]^T + b1 + bs02) -> A2cat[:, :1024]
    dan_gemm_kernel<<<grid, block, SMEM_TOTAL>>>(
        A1h, A1l, B1h, B1l, 2048, 32, b1, bs02,
        Dw1, Db1, Dw2, Db2, Dw3, Db3, 1, 1,
        nullptr, A2h, A2l, nullptr, nullptr);
    // layer 2: out = DAN([h1|h0] @ [W2|Ws13]^T + b2 + bs13)
    dan_gemm_kernel<<<grid, block, SMEM_TOTAL>>>(
        A2h, A2l, B2h, B2l, 2048, 32, b2, bs13,
        Dw1, Db1, Dw2, Db2, Dw3, Db3, 2, 0,
        out, nullptr, nullptr, nullptr, nullptr);
}

// round 7
// speedup vs baseline: 3.3537x; 1.0003x over previous
#include <cuda_runtime.h>
#include <cuda_bf16.h>
#include <cstdint>

// ============================================================================
// NETWORK_OF_DANS — round 4: split-bf16 HMMA (mma.sync) GEMM + fused DAN
//
// tcgen05 is rejected by this build's compute_103 virtual arch, so the tensor
// path is sm_80-class mma.sync.m16n8k16.bf16 (legal baseline PTX), 3-term
// split-bf16 for fp32-grade accuracy:
//     A@B^T ~= Ah@Bh^T + Ah@Bl^T + Al@Bh^T      (fp32 accumulate)
// Layers are K-concatenated so each layer is ONE GEMM (K = 1024 / 2048).
// DAN (32->15->8->1, lrelu 0.01) runs in the epilogue from registers/smem.
// ============================================================================

#define NTH 256
#define BM 128
#define BN 128
#define BK 64                 // k-chunk in elements (128 B per row)

// ---------------- scratch (bf16 bit patterns as ushort) ---------------------
__device__ unsigned short g_A0h[512 * 1024],  g_A0l[512 * 1024];
__device__ unsigned short g_A1h[512 * 2048],  g_A1l[512 * 2048];
__device__ unsigned short g_A2h[512 * 2048],  g_A2l[512 * 2048];
__device__ unsigned short g_B0h[32768 * 1024], g_B0l[32768 * 1024];
__device__ unsigned short g_B1h[32768 * 2048], g_B1l[32768 * 2048];
__device__ unsigned short g_B2h[32768 * 2048], g_B2l[32768 * 2048];

// ---------------- smem layout (dynamic) -------------------------------------
#define T_AHI 0
#define T_ALO 16384
#define T_BHI 32768
#define T_BLO 49152
#define STG_SZ 65536          // 4 tiles x 128x64 bf16
#define SM_BIAS (3 * STG_SZ)              // 196608: 128 floats
#define SM_DW1  (SM_BIAS + 512)           // 480 floats
#define SM_DB1  (SM_DW1 + 1920)           // 15
#define SM_DW2  (SM_DB1 + 64)             // 120
#define SM_DB2  (SM_DW2 + 480)            // 8
#define SM_DW3  (SM_DB2 + 32)             // 8
#define SM_DB3  (SM_DW3 + 32)             // 1
#define SMEM_TOTAL (SM_DB3 + 16)          // ~199.7 KB

#define SWZ(o) ((o) ^ (((o) >> 3) & 0x70))

__device__ __forceinline__ uint32_t smem_u32(const void* p) {
    uint32_t a;
    asm("{ .reg .u64 t; cvta.to.shared.u64 t, %1; cvt.u32.u64 %0, t; }"
        : "=r"(a) : "l"(p));
    return a;
}
__device__ __forceinline__ float lrelu(float v) { return v > 0.0f ? v : 0.01f * v; }

__device__ __forceinline__ void ldsm4(uint32_t* r, uint32_t a) {
    asm volatile("ldmatrix.sync.aligned.m8n8.x4.shared.b16 {%0,%1,%2,%3}, [%4];"
                 : "=r"(r[0]), "=r"(r[1]), "=r"(r[2]), "=r"(r[3]) : "r"(a));
}
__device__ __forceinline__ void mma16816(float* d, const uint32_t* a,
                                         const uint32_t* b) {
    asm volatile(
        "mma.sync.aligned.m16n8k16.row.col.f32.bf16.bf16.f32 "
        "{%0,%1,%2,%3}, {%4,%5,%6,%7}, {%8,%9}, {%0,%1,%2,%3};"
        : "+f"(d[0]), "+f"(d[1]), "+f"(d[2]), "+f"(d[3])
        : "r"(a[0]), "r"(a[1]), "r"(a[2]), "r"(a[3]), "r"(b[0]), "r"(b[1]));
}
__device__ __forceinline__ void cpa16(uint32_t s, const void* g) {
    asm volatile("cp.async.cg.shared.global [%0], [%1], 16;" :: "r"(s), "l"(g));
}
#define CP_COMMIT() asm volatile("cp.async.commit_group;" ::: "memory")
#define CP_WAIT(n)  asm volatile("cp.async.wait_group %0;" :: "n"(n) : "memory")

// ---------------------------------------------------------------------------
// Conversion: f32 [rows,1024] -> bf16 hi (truncated) / lo (RN of residual)
// ---------------------------------------------------------------------------
__global__ __launch_bounds__(256) void conv_split(
    const float* __restrict__ src, unsigned short* __restrict__ dh,
    unsigned short* __restrict__ dl, int dst_ld, int dst_off, int total8)
{
    int idx = blockIdx.x * 256 + threadIdx.x;
    if (idx >= total8) return;
    int r = idx >> 7, c = idx & 127;
    const float4* s = (const float4*)(src + (size_t)r * 1024 + c * 8);
    float4 v0 = s[0], v1 = s[1];

    uint32_t b[8] = {__float_as_uint(v0.x), __float_as_uint(v0.y),
                     __float_as_uint(v0.z), __float_as_uint(v0.w),
                     __float_as_uint(v1.x), __float_as_uint(v1.y),
                     __float_as_uint(v1.z), __float_as_uint(v1.w)};
    float f[8] = {v0.x, v0.y, v0.z, v0.w, v1.x, v1.y, v1.z, v1.w};

    uint4 H;
    H.x = __byte_perm(b[0], b[1], 0x7632);
    H.y = __byte_perm(b[2], b[3], 0x7632);
    H.z = __byte_perm(b[4], b[5], 0x7632);
    H.w = __byte_perm(b[6], b[7], 0x7632);

    float lo[8];
#pragma unroll
    for (int i = 0; i < 8; i++)
        lo[i] = f[i] - __uint_as_float(b[i] & 0xFFFF0000u);

    __nv_bfloat162 l0 = __floats2bfloat162_rn(lo[0], lo[1]);
    __nv_bfloat162 l1 = __floats2bfloat162_rn(lo[2], lo[3]);
    __nv_bfloat162 l2 = __floats2bfloat162_rn(lo[4], lo[5]);
    __nv_bfloat162 l3 = __floats2bfloat162_rn(lo[6], lo[7]);
    uint4 L;
    L.x = *(uint32_t*)&l0; L.y = *(uint32_t*)&l1;
    L.z = *(uint32_t*)&l2; L.w = *(uint32_t*)&l3;

    size_t d = (size_t)r * dst_ld + dst_off + c * 8;
    *(uint4*)(dh + d) = H;
    *(uint4*)(dl + d) = L;
}

// ---------------------------------------------------------------------------
// Fused split-bf16 HMMA GEMM + DAN epilogue.
// Grid (4, 256): bm = bx*128, bn = by*128. 256 threads = 8 warps (2m x 4n),
// warp tile 64x32 (one DAN node wide).
// ---------------------------------------------------------------------------
__global__ __launch_bounds__(NTH, 1) void dan_gemm_kernel(
    const unsigned short* __restrict__ Ah, const unsigned short* __restrict__ Al,
    const unsigned short* __restrict__ Bh, const unsigned short* __restrict__ Bl,
    int ldK, int nchunks,
    const float* __restrict__ bias1, const float* __restrict__ bias2,
    const float* __restrict__ Dw1, const float* __restrict__ Db1,
    const float* __restrict__ Dw2, const float* __restrict__ Db2,
    const float* __restrict__ Dw3, const float* __restrict__ Db3,
    int layer_idx, int mode,                       // 0: fp32 out; 1: bf16 hi/lo
    float* __restrict__ outf,
    unsigned short* __restrict__ oh1, unsigned short* __restrict__ ol1,
    unsigned short* __restrict__ oh2, unsigned short* __restrict__ ol2)
{
    extern __shared__ __align__(1024) char smem[];
    const uint32_t sb = smem_u32(smem);
    const int tid = threadIdx.x;
    const int wid = tid >> 5, lane = tid & 31;
    const int wm = wid >> 2, wn = wid & 3;       // 2 x 4 warp grid
    const int bm = blockIdx.x * BM, bn = blockIdx.y * BN;

    // ---- stage DAN weights + bias ----
    float* sDw1 = (float*)(smem + SM_DW1);
    float* sDb1 = (float*)(smem + SM_DB1);
    float* sDw2 = (float*)(smem + SM_DW2);
    float* sDb2 = (float*)(smem + SM_DB2);
    float* sDw3 = (float*)(smem + SM_DW3);
    float* sDb3 = (float*)(smem + SM_DB3);
    float* sBias = (float*)(smem + SM_BIAS);
    for (int i = tid; i < 15 * 32; i += NTH) sDw1[i] = Dw1[(i >> 5) * 35 + (i & 31)];
    if (tid < 15) sDb1[tid] = Db1[tid] + Dw1[tid * 35 + 32 + layer_idx];
    if (tid >= 32 && tid < 152) sDw2[tid - 32] = Dw2[tid - 32];
    if (tid >= 160 && tid < 168) sDb2[tid - 160] = Db2[tid - 160];
    if (tid >= 168 && tid < 176) sDw3[tid - 168] = Dw3[tid - 168];
    if (tid == 176) sDb3[0] = Db3[0];
    if (tid < 128) sBias[tid] = bias1[bn + tid] + (bias2 ? bias2[bn + tid] : 0.0f);

    // ---- loader: chunk t -> stage s (16B cp.async x 16 per thread) ----
    const int lrow = tid >> 3;          // 0..31 base row step of 32? no: ci layout below
    (void)lrow;
#define LOAD_STAGE(t, s) do {                                                   \
        const uint32_t stg_ = sb + (s) * STG_SZ;                                \
        const int k0_ = (t) * BK;                                               \
        _Pragma("unroll")                                                       \
        for (int j = 0; j < 4; ++j) {                                           \
            int ci = tid + j * NTH;            /* 0..1023 */                    \
            int row = ci >> 3, ch = ci & 7;                                     \
            uint32_t so = SWZ(row * 128 + ch * 16);                             \
            size_t ga = (size_t)(bm + row) * ldK + k0_ + ch * 8;                \
            size_t gb = (size_t)(bn + row) * ldK + k0_ + ch * 8;                \
            cpa16(stg_ + T_AHI + so, Ah + ga);                                  \
            cpa16(stg_ + T_ALO + so, Al + ga);                                  \
            cpa16(stg_ + T_BHI + so, Bh + gb);                                  \
            cpa16(stg_ + T_BLO + so, Bl + gb);                                  \
        }                                                                       \
    } while (0)

    // ---- accumulators ----
    float acc[4][4][4];
#pragma unroll
    for (int i = 0; i < 4; i++)
#pragma unroll
        for (int j = 0; j < 4; j++)
#pragma unroll
            for (int k = 0; k < 4; k++) acc[i][j][k] = 0.0f;

    // per-lane ldmatrix row bases (byte offsets within a 128x64 tile)
    const int rowA = wm * 64 + (lane & 15);
    const int rowB = wn * 32 + ((lane >> 4) & 1) * 8 + (lane & 7);
    const uint32_t baseA = rowA * 128;
    const uint32_t baseB = rowB * 128;
    const int xorv = lane & 7;
    const int chA = lane >> 4;          // 0/1
    const int chB = (lane >> 3) & 1;    // 0/1

    // ---- 3-stage pipeline ----
    LOAD_STAGE(0, 0); CP_COMMIT();
    LOAD_STAGE(1, 1); CP_COMMIT();

    for (int t = 0; t < nchunks; ++t) {
        CP_WAIT(1);
        __syncthreads();
        const int tn = t + 2;
        if (tn < nchunks) { int sl = tn % 3; LOAD_STAGE(tn, sl); }
        CP_COMMIT();

        const uint32_t stg = sb + (t % 3) * STG_SZ;
#pragma unroll
        for (int ks = 0; ks < 4; ++ks) {
            const uint32_t cA = (uint32_t)(((ks * 2 + chA) ^ xorv) << 4);
            const uint32_t cB = (uint32_t)(((ks * 2 + chB) ^ xorv) << 4);
            uint32_t aH[4][4], aL[4][4], bH[2][4], bL[2][4];
#pragma unroll
            for (int mt = 0; mt < 4; ++mt) {
                ldsm4(aH[mt], stg + T_AHI + baseA + mt * 2048 + cA);
                ldsm4(aL[mt], stg + T_ALO + baseA + mt * 2048 + cA);
            }
#pragma unroll
            for (int p = 0; p < 2; ++p) {
                ldsm4(bH[p], stg + T_BHI + baseB + p * 2048 + cB);
                ldsm4(bL[p], stg + T_BLO + baseB + p * 2048 + cB);
            }
#pragma unroll
            for (int mt = 0; mt < 4; ++mt)
#pragma unroll
                for (int nt = 0; nt < 4; ++nt) {
                    const uint32_t* bh = &bH[nt >> 1][(nt & 1) * 2];
                    const uint32_t* bl = &bL[nt >> 1][(nt & 1) * 2];
                    mma16816(acc[mt][nt], aH[mt], bh);
                    mma16816(acc[mt][nt], aH[mt], bl);
                    mma16816(acc[mt][nt], aL[mt], bh);
                }
        }
    }

    // ---- epilogue: stage warp tile (+bias), then per-lane DAN ----
    CP_WAIT(0);
    __syncthreads();

    float* ep = (float*)(smem + wid * 8448);   // [64][33] per warp
    const int r0 = lane >> 2, c0 = (lane & 3) * 2;
#pragma unroll
    for (int mt = 0; mt < 4; ++mt)
#pragma unroll
        for (int nt = 0; nt < 4; ++nt) {
            int rr = mt * 16 + r0, cc = nt * 8 + c0;
            float bx0 = sBias[wn * 32 + cc], bx1 = sBias[wn * 32 + cc + 1];
            ep[rr * 33 + cc]           = acc[mt][nt][0] + bx0;
            ep[rr * 33 + cc + 1]       = acc[mt][nt][1] + bx1;
            ep[(rr + 8) * 33 + cc]     = acc[mt][nt][2] + bx0;
            ep[(rr + 8) * 33 + cc + 1] = acc[mt][nt][3] + bx1;
        }
    __syncwarp();

    const int gnode = (bn >> 5) + wn;
#pragma unroll
    for (int rr = 0; rr < 2; ++rr) {
        const int r = lane * 2 + rr;
        const float* zr = ep + r * 33;
        float h1v[15];
#pragma unroll
        for (int u = 0; u < 15; ++u) {
            float s = sDb1[u];
#pragma unroll
            for (int c = 0; c < 32; ++c) s = fmaf(sDw1[u * 32 + c], zr[c], s);
            h1v[u] = lrelu(s);
        }
        float o = sDb3[0];
#pragma unroll
        for (int v = 0; v < 8; ++v) {
            float s = sDb2[v];
#pragma unroll
            for (int u = 0; u < 15; ++u) s = fmaf(sDw2[v * 15 + u], h1v[u], s);
            o = fmaf(sDw3[v], lrelu(s), o);
        }
        o = lrelu(o);

        const int grow = bm + wm * 64 + r;
        if (mode == 0) {
            outf[(size_t)grow * 1024 + gnode] = o;
        } else {
            uint32_t ob = __float_as_uint(o);
            unsigned short hb = (unsigned short)(ob >> 16);
            float lof = o - __uint_as_float(ob & 0xFFFF0000u);
            __nv_bfloat16 lb16 = __float2bfloat16(lof);
            unsigned short lb = *(unsigned short*)&lb16;
            size_t di = (size_t)grow * 2048 + gnode;
            oh1[di] = hb; ol1[di] = lb;
            if (oh2) { oh2[di + 1024] = hb; ol2[di + 1024] = lb; }
        }
    }
#undef LOAD_STAGE
}

// ---------------------------------------------------------------------------
extern "C" void kernel_launch(void* const* d_in, const int* in_sizes, int n_in,
                              void* d_out, int out_size) {
    (void)in_sizes; (void)n_in; (void)out_size;
    const float* x    = (const float*)d_in[0];
    const float* W0   = (const float*)d_in[1];
    const float* b0   = (const float*)d_in[2];
    const float* W1   = (const float*)d_in[3];
    const float* b1   = (const float*)d_in[4];
    const float* W2   = (const float*)d_in[5];
    const float* b2   = (const float*)d_in[6];
    const float* Ws02 = (const float*)d_in[7];
    const float* bs02 = (const float*)d_in[8];
    const float* Ws13 = (const float*)d_in[9];
    const float* bs13 = (const float*)d_in[10];
    const float* Dw1  = (const float*)d_in[11];
    const float* Db1  = (const float*)d_in[12];
    const float* Dw2  = (const float*)d_in[13];
    const float* Db2  = (const float*)d_in[14];
    const float* Dw3  = (const float*)d_in[15];
    const float* Db3  = (const float*)d_in[16];
    float* out = (float*)d_out;

    unsigned short *A0h, *A0l, *A1h, *A1l, *A2h, *A2l;
    unsigned short *B0h, *B0l, *B1h, *B1l, *B2h, *B2l;
    cudaGetSymbolAddress((void**)&A0h, g_A0h); cudaGetSymbolAddress((void**)&A0l, g_A0l);
    cudaGetSymbolAddress((void**)&A1h, g_A1h); cudaGetSymbolAddress((void**)&A1l, g_A1l);
    cudaGetSymbolAddress((void**)&A2h, g_A2h); cudaGetSymbolAddress((void**)&A2l, g_A2l);
    cudaGetSymbolAddress((void**)&B0h, g_B0h); cudaGetSymbolAddress((void**)&B0l, g_B0l);
    cudaGetSymbolAddress((void**)&B1h, g_B1h); cudaGetSymbolAddress((void**)&B1l, g_B1l);
    cudaGetSymbolAddress((void**)&B2h, g_B2h); cudaGetSymbolAddress((void**)&B2l, g_B2l);

    cudaFuncSetAttribute(dan_gemm_kernel,
                         cudaFuncAttributeMaxDynamicSharedMemorySize, SMEM_TOTAL);

    const int W8 = 32768 * 128;
    const int X8 = 512 * 128;

    conv_split<<<(X8 + 255) / 256, 256>>>(x, A0h, A0l, 1024, 0, X8);
    conv_split<<<(X8 + 255) / 256, 256>>>(x, A1h, A1l, 2048, 1024, X8);
    conv_split<<<(W8 + 255) / 256, 256>>>(W0,   B0h, B0l, 1024, 0,    W8);
    conv_split<<<(W8 + 255) / 256, 256>>>(W1,   B1h, B1l, 2048, 0,    W8);
    conv_split<<<(W8 + 255) / 256, 256>>>(Ws02, B1h, B1l, 2048, 1024, W8);
    conv_split<<<(W8 + 255) / 256, 256>>>(W2,   B2h, B2l, 2048, 0,    W8);
    conv_split<<<(W8 + 255) / 256, 256>>>(Ws13, B2h, B2l, 2048, 1024, W8);

    dim3 grid(4, 256), block(NTH);
    // layer 0: h0 = DAN(x @ W0^T + b0) -> A1cat[:, :1024], A2cat[:, 1024:]
    dan_gemm_kernel<<<grid, block, SMEM_TOTAL>>>(
        A0h, A0l, B0h, B0l, 1024, 16, b0, nullptr,
        Dw1, Db1, Dw2, Db2, Dw3, Db3, 0, 1,
        nullptr, A1h, A1l, A2h, A2l);
    // layer 1: h1 = DAN([h0|x] @ [W1|Ws02]^T + b1 + bs02) -> A2cat[:, :1024]
    dan_gemm_kernel<<<grid, block, SMEM_TOTAL>>>(
        A1h, A1l, B1h, B1l, 2048, 32, b1, bs02,
        Dw1, Db1, Dw2, Db2, Dw3, Db3, 1, 1,
        nullptr, A2h, A2l, nullptr, nullptr);
    // layer 2: out = DAN([h1|h0] @ [W2|Ws13]^T + b2 + bs13)
    dan_gemm_kernel<<<grid, block, SMEM_TOTAL>>>(
        A2h, A2l, B2h, B2l, 2048, 32, b2, bs13,
        Dw1, Db1, Dw2, Db2, Dw3, Db3, 2, 0,
        out, nullptr, nullptr, nullptr, nullptr);
}

// round 8
// speedup vs baseline: 3.4191x; 1.0195x over previous
#include <cuda_runtime.h>
#include <cuda_fp16.h>
#include <cstdint>

// ============================================================================
// NETWORK_OF_DANS — round 7: single-term fp16 HMMA GEMM + fused DAN
//
// Accuracy budget (gate 1e-3, 3-term split measured 7.9e-8) is spent on a
// plain fp16 (RN) GEMM: pre-act rel-err ~2e-4/layer, ~4e-4 end-to-end.
//   pre = A @ B^T + bias      (fp16 inputs, fp32 accum, mma.m16n8k16)
//   h   = DAN(pre)            (32->15->8->1, lrelu 0.01) fused in epilogue
// Layers K-concatenated: each layer is ONE GEMM (K = 1024 / 2048).
// Tile: BM=128 x BN=256, BK=64, 512 thr (16 warps, 2m x 8n, warp 64x32),
// 3-stage cp.async pipeline, XOR-swizzled smem -> conflict-free ldmatrix.
// ============================================================================

#define NTH 512
#define BM 128
#define BN 256
#define BK 64

// ---------------- scratch (fp16 bit patterns as ushort) ---------------------
__device__ unsigned short g_A0[512 * 1024];
__device__ unsigned short g_A1[512 * 2048];
__device__ unsigned short g_A2[512 * 2048];
__device__ unsigned short g_B0[32768 * 1024];
__device__ unsigned short g_B1[32768 * 2048];
__device__ unsigned short g_B2[32768 * 2048];

// ---------------- smem layout (dynamic) -------------------------------------
#define T_A 0                 // 128x64 fp16 = 16 KB
#define T_B 16384             // 256x64 fp16 = 32 KB
#define STG_SZ 49152
#define SM_BIAS (3 * STG_SZ)              // 147456: 256 floats
#define SM_DW1  (SM_BIAS + 1024)
#define SM_DB1  (SM_DW1 + 1920)
#define SM_DW2  (SM_DB1 + 64)
#define SM_DB2  (SM_DW2 + 480)
#define SM_DW3  (SM_DB2 + 32)
#define SM_DB3  (SM_DW3 + 32)
#define SMEM_TOTAL (SM_DB3 + 16)          // ~151 KB

#define SWZ(o) ((o) ^ (((o) >> 3) & 0x70))

__device__ __forceinline__ uint32_t smem_u32(const void* p) {
    uint32_t a;
    asm("{ .reg .u64 t; cvta.to.shared.u64 t, %1; cvt.u32.u64 %0, t; }"
        : "=r"(a) : "l"(p));
    return a;
}
__device__ __forceinline__ float lrelu(float v) { return v > 0.0f ? v : 0.01f * v; }

__device__ __forceinline__ void ldsm4(uint32_t* r, uint32_t a) {
    asm volatile("ldmatrix.sync.aligned.m8n8.x4.shared.b16 {%0,%1,%2,%3}, [%4];"
                 : "=r"(r[0]), "=r"(r[1]), "=r"(r[2]), "=r"(r[3]) : "r"(a));
}
__device__ __forceinline__ void mma16816(float* d, const uint32_t* a,
                                         const uint32_t* b) {
    asm volatile(
        "mma.sync.aligned.m16n8k16.row.col.f32.f16.f16.f32 "
        "{%0,%1,%2,%3}, {%4,%5,%6,%7}, {%8,%9}, {%0,%1,%2,%3};"
        : "+f"(d[0]), "+f"(d[1]), "+f"(d[2]), "+f"(d[3])
        : "r"(a[0]), "r"(a[1]), "r"(a[2]), "r"(a[3]), "r"(b[0]), "r"(b[1]));
}
__device__ __forceinline__ void cpa16(uint32_t s, const void* g) {
    asm volatile("cp.async.cg.shared.global [%0], [%1], 16;" :: "r"(s), "l"(g));
}
#define CP_COMMIT() asm volatile("cp.async.commit_group;" ::: "memory")
#define CP_WAIT(n)  asm volatile("cp.async.wait_group %0;" :: "n"(n) : "memory")

// ---------------------------------------------------------------------------
// Conversion: f32 [rows,1024] -> fp16 RN at column offset in dst (ld dst_ld)
// ---------------------------------------------------------------------------
__global__ __launch_bounds__(256) void conv_h(
    const float* __restrict__ src, unsigned short* __restrict__ dst,
    int dst_ld, int dst_off, int total8)
{
    int idx = blockIdx.x * 256 + threadIdx.x;
    if (idx >= total8) return;
    int r = idx >> 7, c = idx & 127;
    const float4* s = (const float4*)(src + (size_t)r * 1024 + c * 8);
    float4 v0 = s[0], v1 = s[1];

    __half2 h0 = __floats2half2_rn(v0.x, v0.y);
    __half2 h1 = __floats2half2_rn(v0.z, v0.w);
    __half2 h2 = __floats2half2_rn(v1.x, v1.y);
    __half2 h3 = __floats2half2_rn(v1.z, v1.w);
    uint4 H;
    H.x = *(uint32_t*)&h0; H.y = *(uint32_t*)&h1;
    H.z = *(uint32_t*)&h2; H.w = *(uint32_t*)&h3;

    *(uint4*)(dst + (size_t)r * dst_ld + dst_off + c * 8) = H;
}

// ---------------------------------------------------------------------------
// Fused fp16 HMMA GEMM + DAN epilogue.
// Grid (4, 128): bm = bx*128, bn = by*256. 512 threads = 16 warps (2m x 8n),
// warp tile 64x32 (one DAN node wide).
// ---------------------------------------------------------------------------
__global__ __launch_bounds__(NTH, 1) void dan_gemm_kernel(
    const unsigned short* __restrict__ Ah, const unsigned short* __restrict__ Bh,
    int ldK, int nchunks,
    const float* __restrict__ bias1, const float* __restrict__ bias2,
    const float* __restrict__ Dw1, const float* __restrict__ Db1,
    const float* __restrict__ Dw2, const float* __restrict__ Db2,
    const float* __restrict__ Dw3, const float* __restrict__ Db3,
    int layer_idx, int mode,                       // 0: fp32 out; 1: fp16 h out
    float* __restrict__ outf,
    unsigned short* __restrict__ oh1, unsigned short* __restrict__ oh2)
{
    extern __shared__ __align__(1024) char smem[];
    const uint32_t sb = smem_u32(smem);
    const int tid = threadIdx.x;
    const int wid = tid >> 5, lane = tid & 31;
    const int wm = wid >> 3, wn = wid & 7;       // 2 x 8 warp grid
    const int bm = blockIdx.x * BM, bn = blockIdx.y * BN;

    // ---- stage DAN weights + bias ----
    float* sDw1 = (float*)(smem + SM_DW1);
    float* sDb1 = (float*)(smem + SM_DB1);
    float* sDw2 = (float*)(smem + SM_DW2);
    float* sDb2 = (float*)(smem + SM_DB2);
    float* sDw3 = (float*)(smem + SM_DW3);
    float* sDb3 = (float*)(smem + SM_DB3);
    float* sBias = (float*)(smem + SM_BIAS);
    for (int i = tid; i < 15 * 32; i += NTH) sDw1[i] = Dw1[(i >> 5) * 35 + (i & 31)];
    if (tid < 15) sDb1[tid] = Db1[tid] + Dw1[tid * 35 + 32 + layer_idx];
    if (tid >= 32 && tid < 152) sDw2[tid - 32] = Dw2[tid - 32];
    if (tid >= 160 && tid < 168) sDb2[tid - 160] = Db2[tid - 160];
    if (tid >= 168 && tid < 176) sDw3[tid - 168] = Dw3[tid - 168];
    if (tid == 176) sDb3[0] = Db3[0];
    if (tid < 256) sBias[tid] = bias1[bn + tid] + (bias2 ? bias2[bn + tid] : 0.0f);

#define LOAD_STAGE(t, s) do {                                                   \
        const uint32_t stg_ = sb + (s) * STG_SZ;                                \
        const int k0_ = (t) * BK;                                               \
        _Pragma("unroll")                                                       \
        for (int j = 0; j < 2; ++j) {        /* A: 1024 chunks */               \
            int ci = tid + j * NTH;                                             \
            int row = ci >> 3, ch = ci & 7;                                     \
            cpa16(stg_ + T_A + SWZ(row * 128 + ch * 16),                        \
                  Ah + (size_t)(bm + row) * ldK + k0_ + ch * 8);                \
        }                                                                       \
        _Pragma("unroll")                                                       \
        for (int j = 0; j < 4; ++j) {        /* B: 2048 chunks */               \
            int ci = tid + j * NTH;                                             \
            int row = ci >> 3, ch = ci & 7;                                     \
            cpa16(stg_ + T_B + SWZ(row * 128 + ch * 16),                        \
                  Bh + (size_t)(bn + row) * ldK + k0_ + ch * 8);                \
        }                                                                       \
    } while (0)

    // ---- accumulators ----
    float acc[4][4][4];
#pragma unroll
    for (int i = 0; i < 4; i++)
#pragma unroll
        for (int j = 0; j < 4; j++)
#pragma unroll
            for (int k = 0; k < 4; k++) acc[i][j][k] = 0.0f;

    const uint32_t baseA = (uint32_t)((wm * 64 + (lane & 15)) * 128);
    const uint32_t baseB = (uint32_t)((wn * 32 + ((lane >> 4) & 1) * 8 + (lane & 7)) * 128);
    const int xorv = lane & 7;
    const int chA = lane >> 4;          // 0/1
    const int chB = (lane >> 3) & 1;    // 0/1

    // ---- 3-stage pipeline ----
    LOAD_STAGE(0, 0); CP_COMMIT();
    LOAD_STAGE(1, 1); CP_COMMIT();

    for (int t = 0; t < nchunks; ++t) {
        CP_WAIT(1);
        __syncthreads();
        const int tn = t + 2;
        if (tn < nchunks) { int sl = tn % 3; LOAD_STAGE(tn, sl); }
        CP_COMMIT();

        const uint32_t stg = sb + (t % 3) * STG_SZ;
#pragma unroll
        for (int ks = 0; ks < 4; ++ks) {
            const uint32_t cA = (uint32_t)(((ks * 2 + chA) ^ xorv) << 4);
            const uint32_t cB = (uint32_t)(((ks * 2 + chB) ^ xorv) << 4);
            uint32_t aF[4][4], bF[2][4];
#pragma unroll
            for (int mt = 0; mt < 4; ++mt)
                ldsm4(aF[mt], stg + T_A + baseA + mt * 2048 + cA);
#pragma unroll
            for (int p = 0; p < 2; ++p)
                ldsm4(bF[p], stg + T_B + baseB + p * 2048 + cB);
#pragma unroll
            for (int mt = 0; mt < 4; ++mt)
#pragma unroll
                for (int nt = 0; nt < 4; ++nt)
                    mma16816(acc[mt][nt], aF[mt], &bF[nt >> 1][(nt & 1) * 2]);
        }
    }

    // ---- epilogue: stage warp tile (+bias) into (reused) stage smem ----
    CP_WAIT(0);
    __syncthreads();

    float* ep = (float*)(smem + wid * 8448);   // [64][33] per warp, < 3*STG_SZ
    const int r0 = lane >> 2, c0 = (lane & 3) * 2;
#pragma unroll
    for (int mt = 0; mt < 4; ++mt)
#pragma unroll
        for (int nt = 0; nt < 4; ++nt) {
            int rr = mt * 16 + r0, cc = nt * 8 + c0;
            float bx0 = sBias[wn * 32 + cc], bx1 = sBias[wn * 32 + cc + 1];
            ep[rr * 33 + cc]           = acc[mt][nt][0] + bx0;
            ep[rr * 33 + cc + 1]       = acc[mt][nt][1] + bx1;
            ep[(rr + 8) * 33 + cc]     = acc[mt][nt][2] + bx0;
            ep[(rr + 8) * 33 + cc + 1] = acc[mt][nt][3] + bx1;
        }
    __syncwarp();

    const int gnode = (bn >> 5) + wn;
#pragma unroll
    for (int rr = 0; rr < 2; ++rr) {
        const int r = lane * 2 + rr;
        const float* zr = ep + r * 33;
        float h1v[15];
#pragma unroll
        for (int u = 0; u < 15; ++u) {
            float s = sDb1[u];
#pragma unroll
            for (int c = 0; c < 32; ++c) s = fmaf(sDw1[u * 32 + c], zr[c], s);
            h1v[u] = lrelu(s);
        }
        float o = sDb3[0];
#pragma unroll
        for (int v = 0; v < 8; ++v) {
            float s = sDb2[v];
#pragma unroll
            for (int u = 0; u < 15; ++u) s = fmaf(sDw2[v * 15 + u], h1v[u], s);
            o = fmaf(sDw3[v], lrelu(s), o);
        }
        o = lrelu(o);

        const int grow = bm + wm * 64 + r;
        if (mode == 0) {
            outf[(size_t)grow * 1024 + gnode] = o;
        } else {
            __half oh = __float2half_rn(o);
            unsigned short hb = *(unsigned short*)&oh;
            size_t di = (size_t)grow * 2048 + gnode;
            oh1[di] = hb;
            if (oh2) oh2[di + 1024] = hb;
        }
    }
#undef LOAD_STAGE
}

// ---------------------------------------------------------------------------
extern "C" void kernel_launch(void* const* d_in, const int* in_sizes, int n_in,
                              void* d_out, int out_size) {
    (void)in_sizes; (void)n_in; (void)out_size;
    const float* x    = (const float*)d_in[0];
    const float* W0   = (const float*)d_in[1];
    const float* b0   = (const float*)d_in[2];
    const float* W1   = (const float*)d_in[3];
    const float* b1   = (const float*)d_in[4];
    const float* W2   = (const float*)d_in[5];
    const float* b2   = (const float*)d_in[6];
    const float* Ws02 = (const float*)d_in[7];
    const float* bs02 = (const float*)d_in[8];
    const float* Ws13 = (const float*)d_in[9];
    const float* bs13 = (const float*)d_in[10];
    const float* Dw1  = (const float*)d_in[11];
    const float* Db1  = (const float*)d_in[12];
    const float* Dw2  = (const float*)d_in[13];
    const float* Db2  = (const float*)d_in[14];
    const float* Dw3  = (const float*)d_in[15];
    const float* Db3  = (const float*)d_in[16];
    float* out = (float*)d_out;

    unsigned short *A0, *A1, *A2, *B0, *B1, *B2;
    cudaGetSymbolAddress((void**)&A0, g_A0);
    cudaGetSymbolAddress((void**)&A1, g_A1);
    cudaGetSymbolAddress((void**)&A2, g_A2);
    cudaGetSymbolAddress((void**)&B0, g_B0);
    cudaGetSymbolAddress((void**)&B1, g_B1);
    cudaGetSymbolAddress((void**)&B2, g_B2);

    cudaFuncSetAttribute(dan_gemm_kernel,
                         cudaFuncAttributeMaxDynamicSharedMemorySize, SMEM_TOTAL);

    const int W8 = 32768 * 128;
    const int X8 = 512 * 128;

    conv_h<<<(X8 + 255) / 256, 256>>>(x, A0, 1024, 0, X8);
    conv_h<<<(X8 + 255) / 256, 256>>>(x, A1, 2048, 1024, X8);     // [h0 | x]
    conv_h<<<(W8 + 255) / 256, 256>>>(W0,   B0, 1024, 0,    W8);
    conv_h<<<(W8 + 255) / 256, 256>>>(W1,   B1, 2048, 0,    W8);
    conv_h<<<(W8 + 255) / 256, 256>>>(Ws02, B1, 2048, 1024, W8);
    conv_h<<<(W8 + 255) / 256, 256>>>(W2,   B2, 2048, 0,    W8);
    conv_h<<<(W8 + 255) / 256, 256>>>(Ws13, B2, 2048, 1024, W8);

    dim3 grid(4, 128), block(NTH);
    // layer 0: h0 = DAN(x @ W0^T + b0) -> A1[:, :1024], A2[:, 1024:]
    dan_gemm_kernel<<<grid, block, SMEM_TOTAL>>>(
        A0, B0, 1024, 16, b0, nullptr,
        Dw1, Db1, Dw2, Db2, Dw3, Db3, 0, 1, nullptr, A1, A2);
    // layer 1: h1 = DAN([h0|x] @ [W1|Ws02]^T + b1 + bs02) -> A2[:, :1024]
    dan_gemm_kernel<<<grid, block, SMEM_TOTAL>>>(
        A1, B1, 2048, 32, b1, bs02,
        Dw1, Db1, Dw2, Db2, Dw3, Db3, 1, 1, nullptr, A2, nullptr);
    // layer 2: out = DAN([h1|h0] @ [W2|Ws13]^T + b2 + bs13)
    dan_gemm_kernel<<<grid, block, SMEM_TOTAL>>>(
        A2, B2, 2048, 32, b2, bs13,
        Dw1, Db1, Dw2, Db2, Dw3, Db3, 2, 0, out, nullptr, nullptr);
}

// round 9
// speedup vs baseline: 6.3637x; 1.8612x over previous
#include <cuda_runtime.h>
#include <cuda_fp16.h>
#include <cstdint>

// ============================================================================
// NETWORK_OF_DANS — round 9: fp16 HMMA GEMM @ 2 CTAs/SM + fused DAN + 1 conv
//
//   pre = A @ B^T + bias      (fp16 RN inputs, fp32 accum, mma.m16n8k16)
//   h   = DAN(pre)            (32->15->8->1, lrelu 0.01) fused in epilogue
// Layers K-concatenated: each layer ONE GEMM (K = 1024 / 2048).
// Tile: BM=128 x BN=128, BK=64, 256 thr (8 warps, 2m x 4n, warp 64x32 = one
// DAN node wide), 3-stage cp.async pipeline (96KB stages), smem 101.4 KB/CTA
// -> 2 CTAs/SM so per-chunk barrier/wait bubbles overlap across CTAs.
// All 7 fp32->fp16 conversions fused into ONE kernel (region table in args).
// ============================================================================

#define NTH 256
#define BM 128
#define BN 128
#define BK 64

// ---------------- scratch (fp16 bit patterns as ushort) ---------------------
__device__ unsigned short g_A0[512 * 1024];
__device__ unsigned short g_A1[512 * 2048];
__device__ unsigned short g_A2[512 * 2048];
__device__ unsigned short g_B0[32768 * 1024];
__device__ unsigned short g_B1[32768 * 2048];
__device__ unsigned short g_B2[32768 * 2048];

// ---------------- smem layout (dynamic) -------------------------------------
#define T_A 0                 // 128x64 fp16 = 16 KB
#define T_B 16384             // 128x64 fp16 = 16 KB
#define STG_SZ 32768
#define SM_BIAS (3 * STG_SZ)              // 98304: 128 floats
#define SM_DW1  (SM_BIAS + 512)
#define SM_DB1  (SM_DW1 + 1920)
#define SM_DW2  (SM_DB1 + 64)
#define SM_DB2  (SM_DW2 + 480)
#define SM_DW3  (SM_DB2 + 32)
#define SM_DB3  (SM_DW3 + 32)
#define SMEM_TOTAL (SM_DB3 + 16)          // 101360 B -> 2 CTAs/SM

#define SWZ(o) ((o) ^ (((o) >> 3) & 0x70))

__device__ __forceinline__ uint32_t smem_u32(const void* p) {
    uint32_t a;
    asm("{ .reg .u64 t; cvta.to.shared.u64 t, %1; cvt.u32.u64 %0, t; }"
        : "=r"(a) : "l"(p));
    return a;
}
__device__ __forceinline__ float lrelu(float v) { return v > 0.0f ? v : 0.01f * v; }

__device__ __forceinline__ void ldsm4(uint32_t* r, uint32_t a) {
    asm volatile("ldmatrix.sync.aligned.m8n8.x4.shared.b16 {%0,%1,%2,%3}, [%4];"
                 : "=r"(r[0]), "=r"(r[1]), "=r"(r[2]), "=r"(r[3]) : "r"(a));
}
__device__ __forceinline__ void mma16816(float* d, const uint32_t* a,
                                         const uint32_t* b) {
    asm volatile(
        "mma.sync.aligned.m16n8k16.row.col.f32.f16.f16.f32 "
        "{%0,%1,%2,%3}, {%4,%5,%6,%7}, {%8,%9}, {%0,%1,%2,%3};"
        : "+f"(d[0]), "+f"(d[1]), "+f"(d[2]), "+f"(d[3])
        : "r"(a[0]), "r"(a[1]), "r"(a[2]), "r"(a[3]), "r"(b[0]), "r"(b[1]));
}
__device__ __forceinline__ void cpa16(uint32_t s, const void* g) {
    asm volatile("cp.async.cg.shared.global [%0], [%1], 16;" :: "r"(s), "l"(g));
}
#define CP_COMMIT() asm volatile("cp.async.commit_group;" ::: "memory")
#define CP_WAIT(n)  asm volatile("cp.async.wait_group %0;" :: "n"(n) : "memory")

// ---------------------------------------------------------------------------
// Fused conversion: 7 regions, one launch.
// Regions 0..4: W matrices (32768x1024 f32). Regions 5,6: x (512x1024 f32).
// ---------------------------------------------------------------------------
struct ConvArgs {
    const float* src[7];
    unsigned short* dst[7];
    int ld[7];
    int off[7];
};

#define WBLK 16384      // blocks per W region (32768*1024/8/256)
#define XBLK 256        // blocks per x region
#define CONV_GRID (5 * WBLK + 2 * XBLK)

__global__ __launch_bounds__(256) void conv_fused(ConvArgs a) {
    int b = blockIdx.x;
    int reg, sub;
    if (b < 5 * WBLK) { reg = b / WBLK;           sub = b % WBLK; }
    else              { reg = 5 + (b - 5 * WBLK) / XBLK; sub = (b - 5 * WBLK) % XBLK; }

    int idx = sub * 256 + threadIdx.x;
    int r = idx >> 7, c = idx & 127;

    const float4* s = (const float4*)(a.src[reg] + (size_t)r * 1024 + c * 8);
    float4 v0 = s[0], v1 = s[1];

    __half2 h0 = __floats2half2_rn(v0.x, v0.y);
    __half2 h1 = __floats2half2_rn(v0.z, v0.w);
    __half2 h2 = __floats2half2_rn(v1.x, v1.y);
    __half2 h3 = __floats2half2_rn(v1.z, v1.w);
    uint4 H;
    H.x = *(uint32_t*)&h0; H.y = *(uint32_t*)&h1;
    H.z = *(uint32_t*)&h2; H.w = *(uint32_t*)&h3;

    *(uint4*)(a.dst[reg] + (size_t)r * a.ld[reg] + a.off[reg] + c * 8) = H;
}

// ---------------------------------------------------------------------------
// Fused fp16 HMMA GEMM + DAN epilogue.
// Grid (4, 256): bm = bx*128, bn = by*128. 256 thr = 8 warps (2m x 4n).
// ---------------------------------------------------------------------------
__global__ __launch_bounds__(NTH, 2) void dan_gemm_kernel(
    const unsigned short* __restrict__ Ah, const unsigned short* __restrict__ Bh,
    int ldK, int nchunks,
    const float* __restrict__ bias1, const float* __restrict__ bias2,
    const float* __restrict__ Dw1, const float* __restrict__ Db1,
    const float* __restrict__ Dw2, const float* __restrict__ Db2,
    const float* __restrict__ Dw3, const float* __restrict__ Db3,
    int layer_idx, int mode,                       // 0: fp32 out; 1: fp16 h out
    float* __restrict__ outf,
    unsigned short* __restrict__ oh1, unsigned short* __restrict__ oh2)
{
    extern __shared__ __align__(1024) char smem[];
    const uint32_t sb = smem_u32(smem);
    const int tid = threadIdx.x;
    const int wid = tid >> 5, lane = tid & 31;
    const int wm = wid >> 2, wn = wid & 3;       // 2 x 4 warp grid
    const int bm = blockIdx.x * BM, bn = blockIdx.y * BN;

    // ---- stage DAN weights + bias ----
    float* sDw1 = (float*)(smem + SM_DW1);
    float* sDb1 = (float*)(smem + SM_DB1);
    float* sDw2 = (float*)(smem + SM_DW2);
    float* sDb2 = (float*)(smem + SM_DB2);
    float* sDw3 = (float*)(smem + SM_DW3);
    float* sDb3 = (float*)(smem + SM_DB3);
    float* sBias = (float*)(smem + SM_BIAS);
    for (int i = tid; i < 15 * 32; i += NTH) sDw1[i] = Dw1[(i >> 5) * 35 + (i & 31)];
    if (tid < 15) sDb1[tid] = Db1[tid] + Dw1[tid * 35 + 32 + layer_idx];
    if (tid >= 32 && tid < 152) sDw2[tid - 32] = Dw2[tid - 32];
    if (tid >= 160 && tid < 168) sDb2[tid - 160] = Db2[tid - 160];
    if (tid >= 168 && tid < 176) sDw3[tid - 168] = Dw3[tid - 168];
    if (tid == 176) sDb3[0] = Db3[0];
    if (tid < 128) sBias[tid] = bias1[bn + tid] + (bias2 ? bias2[bn + tid] : 0.0f);

#define LOAD_STAGE(t, s) do {                                                   \
        const uint32_t stg_ = sb + (s) * STG_SZ;                                \
        const int k0_ = (t) * BK;                                               \
        _Pragma("unroll")                                                       \
        for (int j = 0; j < 4; ++j) {        /* A: 1024 16B-chunks */           \
            int ci = tid + j * NTH;                                             \
            int row = ci >> 3, ch = ci & 7;                                     \
            cpa16(stg_ + T_A + SWZ(row * 128 + ch * 16),                        \
                  Ah + (size_t)(bm + row) * ldK + k0_ + ch * 8);                \
        }                                                                       \
        _Pragma("unroll")                                                       \
        for (int j = 0; j < 4; ++j) {        /* B: 1024 16B-chunks */           \
            int ci = tid + j * NTH;                                             \
            int row = ci >> 3, ch = ci & 7;                                     \
            cpa16(stg_ + T_B + SWZ(row * 128 + ch * 16),                        \
                  Bh + (size_t)(bn + row) * ldK + k0_ + ch * 8);                \
        }                                                                       \
    } while (0)

    // ---- accumulators ----
    float acc[4][4][4];
#pragma unroll
    for (int i = 0; i < 4; i++)
#pragma unroll
        for (int j = 0; j < 4; j++)
#pragma unroll
            for (int k = 0; k < 4; k++) acc[i][j][k] = 0.0f;

    const uint32_t baseA = (uint32_t)((wm * 64 + (lane & 15)) * 128);
    const uint32_t baseB = (uint32_t)((wn * 32 + ((lane >> 4) & 1) * 8 + (lane & 7)) * 128);
    const int xorv = lane & 7;
    const int chA = lane >> 4;          // 0/1
    const int chB = (lane >> 3) & 1;    // 0/1

    // ---- 3-stage pipeline ----
    LOAD_STAGE(0, 0); CP_COMMIT();
    LOAD_STAGE(1, 1); CP_COMMIT();

    for (int t = 0; t < nchunks; ++t) {
        CP_WAIT(1);
        __syncthreads();
        const int tn = t + 2;
        if (tn < nchunks) { int sl = tn % 3; LOAD_STAGE(tn, sl); }
        CP_COMMIT();

        const uint32_t stg = sb + (t % 3) * STG_SZ;
#pragma unroll
        for (int ks = 0; ks < 4; ++ks) {
            const uint32_t cA = (uint32_t)(((ks * 2 + chA) ^ xorv) << 4);
            const uint32_t cB = (uint32_t)(((ks * 2 + chB) ^ xorv) << 4);
            uint32_t aF[4][4], bF[2][4];
#pragma unroll
            for (int mt = 0; mt < 4; ++mt)
                ldsm4(aF[mt], stg + T_A + baseA + mt * 2048 + cA);
#pragma unroll
            for (int p = 0; p < 2; ++p)
                ldsm4(bF[p], stg + T_B + baseB + p * 2048 + cB);
#pragma unroll
            for (int mt = 0; mt < 4; ++mt)
#pragma unroll
                for (int nt = 0; nt < 4; ++nt)
                    mma16816(acc[mt][nt], aF[mt], &bF[nt >> 1][(nt & 1) * 2]);
        }
    }

    // ---- epilogue: stage warp tile (+bias) into (reused) stage smem ----
    CP_WAIT(0);
    __syncthreads();

    float* ep = (float*)(smem + wid * 8448);   // [64][33] per warp (67.6KB < 96KB)
    const int r0 = lane >> 2, c0 = (lane & 3) * 2;
#pragma unroll
    for (int mt = 0; mt < 4; ++mt)
#pragma unroll
        for (int nt = 0; nt < 4; ++nt) {
            int rr = mt * 16 + r0, cc = nt * 8 + c0;
            float bx0 = sBias[wn * 32 + cc], bx1 = sBias[wn * 32 + cc + 1];
            ep[rr * 33 + cc]           = acc[mt][nt][0] + bx0;
            ep[rr * 33 + cc + 1]       = acc[mt][nt][1] + bx1;
            ep[(rr + 8) * 33 + cc]     = acc[mt][nt][2] + bx0;
            ep[(rr + 8) * 33 + cc + 1] = acc[mt][nt][3] + bx1;
        }
    __syncwarp();

    const int gnode = (bn >> 5) + wn;
#pragma unroll
    for (int rr = 0; rr < 2; ++rr) {
        const int r = lane * 2 + rr;
        const float* zr = ep + r * 33;
        float h1v[15];
#pragma unroll
        for (int u = 0; u < 15; ++u) {
            float s = sDb1[u];
#pragma unroll
            for (int c = 0; c < 32; ++c) s = fmaf(sDw1[u * 32 + c], zr[c], s);
            h1v[u] = lrelu(s);
        }
        float o = sDb3[0];
#pragma unroll
        for (int v = 0; v < 8; ++v) {
            float s = sDb2[v];
#pragma unroll
            for (int u = 0; u < 15; ++u) s = fmaf(sDw2[v * 15 + u], h1v[u], s);
            o = fmaf(sDw3[v], lrelu(s), o);
        }
        o = lrelu(o);

        const int grow = bm + wm * 64 + r;
        if (mode == 0) {
            outf[(size_t)grow * 1024 + gnode] = o;
        } else {
            __half oh = __float2half_rn(o);
            unsigned short hb = *(unsigned short*)&oh;
            size_t di = (size_t)grow * 2048 + gnode;
            oh1[di] = hb;
            if (oh2) oh2[di + 1024] = hb;
        }
    }
#undef LOAD_STAGE
}

// ---------------------------------------------------------------------------
extern "C" void kernel_launch(void* const* d_in, const int* in_sizes, int n_in,
                              void* d_out, int out_size) {
    (void)in_sizes; (void)n_in; (void)out_size;
    const float* x    = (const float*)d_in[0];
    const float* W0   = (const float*)d_in[1];
    const float* b0   = (const float*)d_in[2];
    const float* W1   = (const float*)d_in[3];
    const float* b1   = (const float*)d_in[4];
    const float* W2   = (const float*)d_in[5];
    const float* b2   = (const float*)d_in[6];
    const float* Ws02 = (const float*)d_in[7];
    const float* bs02 = (const float*)d_in[8];
    const float* Ws13 = (const float*)d_in[9];
    const float* bs13 = (const float*)d_in[10];
    const float* Dw1  = (const float*)d_in[11];
    const float* Db1  = (const float*)d_in[12];
    const float* Dw2  = (const float*)d_in[13];
    const float* Db2  = (const float*)d_in[14];
    const float* Dw3  = (const float*)d_in[15];
    const float* Db3  = (const float*)d_in[16];
    float* out = (float*)d_out;

    unsigned short *A0, *A1, *A2, *B0, *B1, *B2;
    cudaGetSymbolAddress((void**)&A0, g_A0);
    cudaGetSymbolAddress((void**)&A1, g_A1);
    cudaGetSymbolAddress((void**)&A2, g_A2);
    cudaGetSymbolAddress((void**)&B0, g_B0);
    cudaGetSymbolAddress((void**)&B1, g_B1);
    cudaGetSymbolAddress((void**)&B2, g_B2);

    cudaFuncSetAttribute(dan_gemm_kernel,
                         cudaFuncAttributeMaxDynamicSharedMemorySize, SMEM_TOTAL);

    // one fused conversion launch (5 W regions + 2 x regions)
    ConvArgs ca;
    ca.src[0] = W0;   ca.dst[0] = B0; ca.ld[0] = 1024; ca.off[0] = 0;
    ca.src[1] = W1;   ca.dst[1] = B1; ca.ld[1] = 2048; ca.off[1] = 0;
    ca.src[2] = Ws02; ca.dst[2] = B1; ca.ld[2] = 2048; ca.off[2] = 1024;
    ca.src[3] = W2;   ca.dst[3] = B2; ca.ld[3] = 2048; ca.off[3] = 0;
    ca.src[4] = Ws13; ca.dst[4] = B2; ca.ld[4] = 2048; ca.off[4] = 1024;
    ca.src[5] = x;    ca.dst[5] = A0; ca.ld[5] = 1024; ca.off[5] = 0;
    ca.src[6] = x;    ca.dst[6] = A1; ca.ld[6] = 2048; ca.off[6] = 1024;  // [h0|x]
    conv_fused<<<CONV_GRID, 256>>>(ca);

    dim3 grid(4, 256), block(NTH);
    // layer 0: h0 = DAN(x @ W0^T + b0) -> A1[:, :1024], A2[:, 1024:]
    dan_gemm_kernel<<<grid, block, SMEM_TOTAL>>>(
        A0, B0, 1024, 16, b0, nullptr,
        Dw1, Db1, Dw2, Db2, Dw3, Db3, 0, 1, nullptr, A1, A2);
    // layer 1: h1 = DAN([h0|x] @ [W1|Ws02]^T + b1 + bs02) -> A2[:, :1024]
    dan_gemm_kernel<<<grid, block, SMEM_TOTAL>>>(
        A1, B1, 2048, 32, b1, bs02,
        Dw1, Db1, Dw2, Db2, Dw3, Db3, 1, 1, nullptr, A2, nullptr);
    // layer 2: out = DAN([h1|h0] @ [W2|Ws13]^T + b2 + bs13)
    dan_gemm_kernel<<<grid, block, SMEM_TOTAL>>>(
        A2, B2, 2048, 32, b2, bs13,
        Dw1, Db1, Dw2, Db2, Dw3, Db3, 2, 0, out, nullptr, nullptr);
}

// round 10
// speedup vs baseline: 9.2531x; 1.4541x over previous
#include <cuda_runtime.h>
#include <cuda_fp16.h>
#include <cstdint>

// ============================================================================
// NETWORK_OF_DANS — round 10: Dw1 folded into weights (N halves) + fp16 HMMA
//
// DAN layer 1 is linear pre-lrelu, so per 32-channel node:
//     pre15 = Dw1[:, :32] @ (W_node a + b_node) + Db1 + Dw1[:, 32+l]
//           = (Dw1 @ W_node) a + b15_node
// Fold pass computes W' = Dw1 @ W (15 rows, padded to 16) in fp16; GEMM N
// drops 32768 -> 16384 (2x less mma + ldsm + barriers). b15 per node is
// computed in the GEMM prologue. Epilogue: lrelu(pre15) -> 15->8->1 DAN tail.
// GEMM: BM=128 x BN=128, BK=64, 8 warps (2x4, warp 64x32), 3-stage cp.async,
// 2 CTAs/SM; co-resident CTAs staggered in k-phase by (by&1)*nchunks/2.
// ============================================================================

#define NTH 256
#define BM 128
#define BN 128
#define BK 64

// ---------------- scratch (fp16 bit patterns as ushort) ---------------------
__device__ unsigned short g_A0[512 * 1024];
__device__ unsigned short g_A1[512 * 2048];
__device__ unsigned short g_A2[512 * 2048];
__device__ unsigned short g_B0[16384 * 1024];
__device__ unsigned short g_B1[16384 * 2048];
__device__ unsigned short g_B2[16384 * 2048];

// ---------------- smem layout (dynamic) -------------------------------------
#define T_A 0                 // 128x64 fp16 = 16 KB
#define T_B 16384             // 128x64 fp16 = 16 KB
#define STG_SZ 32768
#define SM_B15  (3 * STG_SZ)              // 98304: 120 floats (8 nodes x 15)
#define SM_DW1  (SM_B15 + 512)
#define SM_DB1  (SM_DW1 + 1920)
#define SM_DW2  (SM_DB1 + 64)
#define SM_DB2  (SM_DW2 + 480)
#define SM_DW3  (SM_DB2 + 32)
#define SM_DB3  (SM_DW3 + 32)
#define SMEM_TOTAL (SM_DB3 + 16)          // ~101 KB -> 2 CTAs/SM

#define SWZ(o) ((o) ^ (((o) >> 3) & 0x70))

__device__ __forceinline__ uint32_t smem_u32(const void* p) {
    uint32_t a;
    asm("{ .reg .u64 t; cvta.to.shared.u64 t, %1; cvt.u32.u64 %0, t; }"
        : "=r"(a) : "l"(p));
    return a;
}
__device__ __forceinline__ float lrelu(float v) { return v > 0.0f ? v : 0.01f * v; }

__device__ __forceinline__ unsigned long long pack2(float lo, float hi) {
    unsigned long long r;
    asm("mov.b64 %0, {%1, %2};" : "=l"(r) : "f"(lo), "f"(hi));
    return r;
}
__device__ __forceinline__ void unpack2(unsigned long long v, float& lo, float& hi) {
    asm("mov.b64 {%0, %1}, %2;" : "=f"(lo), "=f"(hi) : "l"(v));
}
__device__ __forceinline__ void ffma2(unsigned long long& d, unsigned long long a,
                                      unsigned long long b) {
    asm("fma.rn.f32x2 %0, %1, %2, %3;" : "=l"(d) : "l"(a), "l"(b), "l"(d));
}

__device__ __forceinline__ void ldsm4(uint32_t* r, uint32_t a) {
    asm volatile("ldmatrix.sync.aligned.m8n8.x4.shared.b16 {%0,%1,%2,%3}, [%4];"
                 : "=r"(r[0]), "=r"(r[1]), "=r"(r[2]), "=r"(r[3]) : "r"(a));
}
__device__ __forceinline__ void mma16816(float* d, const uint32_t* a,
                                         const uint32_t* b) {
    asm volatile(
        "mma.sync.aligned.m16n8k16.row.col.f32.f16.f16.f32 "
        "{%0,%1,%2,%3}, {%4,%5,%6,%7}, {%8,%9}, {%0,%1,%2,%3};"
        : "+f"(d[0]), "+f"(d[1]), "+f"(d[2]), "+f"(d[3])
        : "r"(a[0]), "r"(a[1]), "r"(a[2]), "r"(a[3]), "r"(b[0]), "r"(b[1]));
}
__device__ __forceinline__ void cpa16(uint32_t s, const void* g) {
    asm volatile("cp.async.cg.shared.global [%0], [%1], 16;" :: "r"(s), "l"(g));
}
#define CP_COMMIT() asm volatile("cp.async.commit_group;" ::: "memory")
#define CP_WAIT(n)  asm volatile("cp.async.wait_group %0;" :: "n"(n) : "memory")

// ---------------------------------------------------------------------------
// Fold: W'[node*16+u, :] = sum_ch Dw1[u,ch] * W[node*32+ch, :], row 15 = 0.
// One block per (region, node); 256 threads x 4 cols. fp32 math via FFMA2,
// output fp16 RN. 5 regions (W0, W1, Ws02, W2, Ws13) with concat ld/off.
// ---------------------------------------------------------------------------
struct FoldArgs {
    const float* src[5];
    unsigned short* dst[5];
    int ld[5];
    int off[5];
};

__global__ __launch_bounds__(256) void fold_w(FoldArgs fa, const float* __restrict__ Dw1g) {
    __shared__ float sDw[15 * 32];
    const int b = blockIdx.x;
    const int reg = b >> 10, node = b & 1023;
    const int tid = threadIdx.x;

    for (int i = tid; i < 15 * 32; i += 256)
        sDw[i] = Dw1g[(i >> 5) * 35 + (i & 31)];
    __syncthreads();

    const float* W = fa.src[reg] + (size_t)node * 32 * 1024 + tid * 4;

    unsigned long long acc2[15][2];
#pragma unroll
    for (int u = 0; u < 15; ++u) { acc2[u][0] = 0ULL; acc2[u][1] = 0ULL; }

#pragma unroll 2
    for (int ch = 0; ch < 32; ++ch) {
        float4 w = *(const float4*)(W + (size_t)ch * 1024);
        unsigned long long p0 = pack2(w.x, w.y), p1 = pack2(w.z, w.w);
#pragma unroll
        for (int u = 0; u < 15; ++u) {
            float dv = sDw[u * 32 + ch];
            unsigned long long d2 = pack2(dv, dv);
            ffma2(acc2[u][0], d2, p0);
            ffma2(acc2[u][1], d2, p1);
        }
    }

    const int ld = fa.ld[reg];
    unsigned short* dst = fa.dst[reg] + (size_t)(node * 16) * ld + fa.off[reg] + tid * 4;
#pragma unroll
    for (int u = 0; u < 15; ++u) {
        float a0, a1, a2, a3;
        unpack2(acc2[u][0], a0, a1);
        unpack2(acc2[u][1], a2, a3);
        __half2 h01 = __floats2half2_rn(a0, a1);
        __half2 h23 = __floats2half2_rn(a2, a3);
        uint2 v;
        v.x = *(uint32_t*)&h01; v.y = *(uint32_t*)&h23;
        *(uint2*)(dst + (size_t)u * ld) = v;
    }
    uint2 z; z.x = 0u; z.y = 0u;
    *(uint2*)(dst + (size_t)15 * ld) = z;     // padded channel
}

// ---------------------------------------------------------------------------
// x conversion: f32 [512,1024] -> fp16 into A0 (ld 1024) and A1 cols 1024..
// ---------------------------------------------------------------------------
__global__ __launch_bounds__(256) void conv_x(
    const float* __restrict__ x, unsigned short* __restrict__ dA0,
    unsigned short* __restrict__ dA1)
{
    int idx = blockIdx.x * 256 + threadIdx.x;   // grid 256 -> 65536 = 512*128
    int r = idx >> 7, c = idx & 127;
    const float4* s = (const float4*)(x + (size_t)r * 1024 + c * 8);
    float4 v0 = s[0], v1 = s[1];
    __half2 h0 = __floats2half2_rn(v0.x, v0.y);
    __half2 h1 = __floats2half2_rn(v0.z, v0.w);
    __half2 h2 = __floats2half2_rn(v1.x, v1.y);
    __half2 h3 = __floats2half2_rn(v1.z, v1.w);
    uint4 H;
    H.x = *(uint32_t*)&h0; H.y = *(uint32_t*)&h1;
    H.z = *(uint32_t*)&h2; H.w = *(uint32_t*)&h3;
    *(uint4*)(dA0 + (size_t)r * 1024 + c * 8) = H;
    *(uint4*)(dA1 + (size_t)r * 2048 + 1024 + c * 8) = H;
}

// ---------------------------------------------------------------------------
// Fused fp16 HMMA GEMM (vs folded W') + DAN tail epilogue.
// Grid (4, 128): bm = bx*128, bn = by*128 (8 original nodes per CTA).
// ---------------------------------------------------------------------------
__global__ __launch_bounds__(NTH, 2) void dan_gemm_kernel(
    const unsigned short* __restrict__ Ah, const unsigned short* __restrict__ Bh,
    int ldK, int nchunks,
    const float* __restrict__ bias1, const float* __restrict__ bias2,
    const float* __restrict__ Dw1, const float* __restrict__ Db1,
    const float* __restrict__ Dw2, const float* __restrict__ Db2,
    const float* __restrict__ Dw3, const float* __restrict__ Db3,
    int layer_idx, int mode,                       // 0: fp32 out; 1: fp16 h out
    float* __restrict__ outf,
    unsigned short* __restrict__ oh1, unsigned short* __restrict__ oh2)
{
    extern __shared__ __align__(1024) char smem[];
    const uint32_t sb = smem_u32(smem);
    const int tid = threadIdx.x;
    const int wid = tid >> 5, lane = tid & 31;
    const int wm = wid >> 2, wn = wid & 3;       // 2 x 4 warp grid
    const int bm = blockIdx.x * BM, bn = blockIdx.y * BN;
    const int n0 = bn >> 4;                      // base original-node id

    // ---- stage DAN weights ----
    float* sB15 = (float*)(smem + SM_B15);
    float* sDw1 = (float*)(smem + SM_DW1);
    float* sDb1 = (float*)(smem + SM_DB1);
    float* sDw2 = (float*)(smem + SM_DW2);
    float* sDb2 = (float*)(smem + SM_DB2);
    float* sDw3 = (float*)(smem + SM_DW3);
    float* sDb3 = (float*)(smem + SM_DB3);
    for (int i = tid; i < 15 * 32; i += NTH) sDw1[i] = Dw1[(i >> 5) * 35 + (i & 31)];
    if (tid < 15) sDb1[tid] = Db1[tid] + Dw1[tid * 35 + 32 + layer_idx];
    if (tid >= 32 && tid < 152) sDw2[tid - 32] = Dw2[tid - 32];
    if (tid >= 160 && tid < 168) sDb2[tid - 160] = Db2[tid - 160];
    if (tid >= 168 && tid < 176) sDw3[tid - 168] = Dw3[tid - 168];
    if (tid == 176) sDb3[0] = Db3[0];

#define LOAD_STAGE(t, s) do {                                                   \
        const uint32_t stg_ = sb + (s) * STG_SZ;                                \
        const int k0_ = (t) * BK;                                               \
        _Pragma("unroll")                                                       \
        for (int j = 0; j < 4; ++j) {        /* A: 1024 16B-chunks */           \
            int ci = tid + j * NTH;                                             \
            int row = ci >> 3, ch = ci & 7;                                     \
            cpa16(stg_ + T_A + SWZ(row * 128 + ch * 16),                        \
                  Ah + (size_t)(bm + row) * ldK + k0_ + ch * 8);                \
        }                                                                       \
        _Pragma("unroll")                                                       \
        for (int j = 0; j < 4; ++j) {        /* B: 1024 16B-chunks */           \
            int ci = tid + j * NTH;                                             \
            int row = ci >> 3, ch = ci & 7;                                     \
            cpa16(stg_ + T_B + SWZ(row * 128 + ch * 16),                        \
                  Bh + (size_t)(bn + row) * ldK + k0_ + ch * 8);                \
        }                                                                       \
    } while (0)

    // k-phase stagger: co-resident CTAs (by, by+37) differ in parity.
    const int koff = (blockIdx.y & 1) * (nchunks >> 1);
#define WRAP(t) ((t) >= nchunks ? (t) - nchunks : (t))

    // ---- accumulators ----
    float acc[4][4][4];
#pragma unroll
    for (int i = 0; i < 4; i++)
#pragma unroll
        for (int j = 0; j < 4; j++)
#pragma unroll
            for (int k = 0; k < 4; k++) acc[i][j][k] = 0.0f;

    const uint32_t baseA = (uint32_t)((wm * 64 + (lane & 15)) * 128);
    const uint32_t baseB = (uint32_t)((wn * 32 + ((lane >> 4) & 1) * 8 + (lane & 7)) * 128);
    const int xorv = lane & 7;
    const int chA = lane >> 4;          // 0/1
    const int chB = (lane >> 3) & 1;    // 0/1

    // ---- 3-stage pipeline ----
    LOAD_STAGE(WRAP(koff), 0); CP_COMMIT();
    LOAD_STAGE(WRAP(koff + 1), 1); CP_COMMIT();
    __syncthreads();     // sDw1/sDb1 visible for b15 fold below

    // ---- per-node 15-vector bias fold (overlaps first stage loads) ----
    if (tid < 120) {
        const int n = tid / 15, u = tid % 15;
        const int gn = (n0 + n) * 32;
        float s = sDb1[u];
#pragma unroll 4
        for (int ch = 0; ch < 32; ++ch) {
            float bt = bias1[gn + ch];
            if (bias2) bt += bias2[gn + ch];
            s = fmaf(sDw1[u * 32 + ch], bt, s);
        }
        sB15[n * 15 + u] = s;
    }

    for (int tt = 0; tt < nchunks; ++tt) {
        CP_WAIT(1);
        __syncthreads();
        const int tn = tt + 2;
        if (tn < nchunks) { int sl = tn % 3; LOAD_STAGE(WRAP(tn + koff), sl); }
        CP_COMMIT();

        const uint32_t stg = sb + (tt % 3) * STG_SZ;
#pragma unroll
        for (int ks = 0; ks < 4; ++ks) {
            const uint32_t cA = (uint32_t)(((ks * 2 + chA) ^ xorv) << 4);
            const uint32_t cB = (uint32_t)(((ks * 2 + chB) ^ xorv) << 4);
            uint32_t aF[4][4], bF[2][4];
#pragma unroll
            for (int mt = 0; mt < 4; ++mt)
                ldsm4(aF[mt], stg + T_A + baseA + mt * 2048 + cA);
#pragma unroll
            for (int p = 0; p < 2; ++p)
                ldsm4(bF[p], stg + T_B + baseB + p * 2048 + cB);
#pragma unroll
            for (int mt = 0; mt < 4; ++mt)
#pragma unroll
                for (int nt = 0; nt < 4; ++nt)
                    mma16816(acc[mt][nt], aF[mt], &bF[nt >> 1][(nt & 1) * 2]);
        }
    }

    // ---- epilogue: stage warp tile (raw pre15), then per-lane DAN tail ----
    CP_WAIT(0);
    __syncthreads();

    float* ep = (float*)(smem + wid * 8448);   // [64][33] per warp (67.6KB)
    const int r0 = lane >> 2, c0 = (lane & 3) * 2;
#pragma unroll
    for (int mt = 0; mt < 4; ++mt)
#pragma unroll
        for (int nt = 0; nt < 4; ++nt) {
            int rr = mt * 16 + r0, cc = nt * 8 + c0;
            ep[rr * 33 + cc]           = acc[mt][nt][0];
            ep[rr * 33 + cc + 1]       = acc[mt][nt][1];
            ep[(rr + 8) * 33 + cc]     = acc[mt][nt][2];
            ep[(rr + 8) * 33 + cc + 1] = acc[mt][nt][3];
        }
    __syncwarp();

#pragma unroll
    for (int ln = 0; ln < 2; ++ln) {            // 2 nodes per warp
        const float* b15 = sB15 + (wn * 2 + ln) * 15;
        const int gnode = n0 + wn * 2 + ln;
#pragma unroll
        for (int rr = 0; rr < 2; ++rr) {
            const int r = lane * 2 + rr;
            const float* zr = ep + r * 33 + ln * 16;
            float h1v[15];
#pragma unroll
            for (int u = 0; u < 15; ++u) h1v[u] = lrelu(zr[u] + b15[u]);
            float o = sDb3[0];
#pragma unroll
            for (int v = 0; v < 8; ++v) {
                float s = sDb2[v];
#pragma unroll
                for (int u = 0; u < 15; ++u) s = fmaf(sDw2[v * 15 + u], h1v[u], s);
                o = fmaf(sDw3[v], lrelu(s), o);
            }
            o = lrelu(o);

            const int grow = bm + wm * 64 + r;
            if (mode == 0) {
                outf[(size_t)grow * 1024 + gnode] = o;
            } else {
                __half oh = __float2half_rn(o);
                unsigned short hb = *(unsigned short*)&oh;
                size_t di = (size_t)grow * 2048 + gnode;
                oh1[di] = hb;
                if (oh2) oh2[di + 1024] = hb;
            }
        }
    }
#undef LOAD_STAGE
#undef WRAP
}

// ---------------------------------------------------------------------------
extern "C" void kernel_launch(void* const* d_in, const int* in_sizes, int n_in,
                              void* d_out, int out_size) {
    (void)in_sizes; (void)n_in; (void)out_size;
    const float* x    = (const float*)d_in[0];
    const float* W0   = (const float*)d_in[1];
    const float* b0   = (const float*)d_in[2];
    const float* W1   = (const float*)d_in[3];
    const float* b1   = (const float*)d_in[4];
    const float* W2   = (const float*)d_in[5];
    const float* b2   = (const float*)d_in[6];
    const float* Ws02 = (const float*)d_in[7];
    const float* bs02 = (const float*)d_in[8];
    const float* Ws13 = (const float*)d_in[9];
    const float* bs13 = (const float*)d_in[10];
    const float* Dw1  = (const float*)d_in[11];
    const float* Db1  = (const float*)d_in[12];
    const float* Dw2  = (const float*)d_in[13];
    const float* Db2  = (const float*)d_in[14];
    const float* Dw3  = (const float*)d_in[15];
    const float* Db3  = (const float*)d_in[16];
    float* out = (float*)d_out;

    unsigned short *A0, *A1, *A2, *B0, *B1, *B2;
    cudaGetSymbolAddress((void**)&A0, g_A0);
    cudaGetSymbolAddress((void**)&A1, g_A1);
    cudaGetSymbolAddress((void**)&A2, g_A2);
    cudaGetSymbolAddress((void**)&B0, g_B0);
    cudaGetSymbolAddress((void**)&B1, g_B1);
    cudaGetSymbolAddress((void**)&B2, g_B2);

    cudaFuncSetAttribute(dan_gemm_kernel,
                         cudaFuncAttributeMaxDynamicSharedMemorySize, SMEM_TOTAL);

    // fold all 5 weight matrices (5 regions x 1024 nodes)
    FoldArgs fa;
    fa.src[0] = W0;   fa.dst[0] = B0; fa.ld[0] = 1024; fa.off[0] = 0;
    fa.src[1] = W1;   fa.dst[1] = B1; fa.ld[1] = 2048; fa.off[1] = 0;
    fa.src[2] = Ws02; fa.dst[2] = B1; fa.ld[2] = 2048; fa.off[2] = 1024;
    fa.src[3] = W2;   fa.dst[3] = B2; fa.ld[3] = 2048; fa.off[3] = 0;
    fa.src[4] = Ws13; fa.dst[4] = B2; fa.ld[4] = 2048; fa.off[4] = 1024;
    fold_w<<<5 * 1024, 256>>>(fa, Dw1);
    conv_x<<<256, 256>>>(x, A0, A1);

    dim3 grid(4, 128), block(NTH);
    // layer 0: h0 = DAN(x @ W0'^T) -> A1[:, :1024], A2[:, 1024:]
    dan_gemm_kernel<<<grid, block, SMEM_TOTAL>>>(
        A0, B0, 1024, 16, b0, nullptr,
        Dw1, Db1, Dw2, Db2, Dw3, Db3, 0, 1, nullptr, A1, A2);
    // layer 1: h1 = DAN([h0|x] @ [W1|Ws02]'^T) -> A2[:, :1024]
    dan_gemm_kernel<<<grid, block, SMEM_TOTAL>>>(
        A1, B1, 2048, 32, b1, bs02,
        Dw1, Db1, Dw2, Db2, Dw3, Db3, 1, 1, nullptr, A2, nullptr);
    // layer 2: out = DAN([h1|h0] @ [W2|Ws13]'^T)
    dan_gemm_kernel<<<grid, block, SMEM_TOTAL>>>(
        A2, B2, 2048, 32, b2, bs13,
        Dw1, Db1, Dw2, Db2, Dw3, Db3, 2, 0, out, nullptr, nullptr);
}